// round 11
// baseline (speedup 1.0000x reference)
#include <cuda_runtime.h>

// ---------------------------------------------------------------------------
// SpatialRangeAttention — GB300 sm_103a
// ---------------------------------------------------------------------------

#define BB   2
#define CC   64
#define HH   112
#define WW   112
#define HWP  (HH*WW)      // 12544
#define NPIX (BB*HWP)     // 25088
#define N2   49
#define PADF 512

// Scratch
__device__ float g_sem_t[NPIX*CC];              // semantic transposed [pix][c]
__device__ float g_px_raw[NPIX*CC + 2*PADF];    // range-proj, channel-major, padded
__device__ float g_nrm_raw[NPIX + 2*PADF];      // per-pixel ||px||^2, padded
__device__ float g_comb[NPIX*N2];               // bilateral / final weights [pix][n]
__device__ float g_gath[NPIX*CC];               // gathered spatial feats [pix][c]

// Interleaved weight buffers (shared by all blocks; L1/L2-resident)
__device__ float2 g_w1r[64*32], g_w2r[64*32];   // range
__device__ float2 g_w1f[113*32], g_w2f[49*32];  // fixup (zero-padded o>=49)
__device__ float2 g_w1o[64*32], g_w2o[64*32];   // output

// 32-FMA block: weight pair a=(w[o],w[o+32]) times 16 pixel x-values
#define ACC32(a, xA, xB, xC, xD)                      \
    y0[0] += a.x*xA.x;  y1[0] += a.y*xA.x;            \
    y0[1] += a.x*xA.y;  y1[1] += a.y*xA.y;            \
    y0[2] += a.x*xA.z;  y1[2] += a.y*xA.z;            \
    y0[3] += a.x*xA.w;  y1[3] += a.y*xA.w;            \
    y0[4] += a.x*xB.x;  y1[4] += a.y*xB.x;            \
    y0[5] += a.x*xB.y;  y1[5] += a.y*xB.y;            \
    y0[6] += a.x*xB.z;  y1[6] += a.y*xB.z;            \
    y0[7] += a.x*xB.w;  y1[7] += a.y*xB.w;            \
    y0[8] += a.x*xC.x;  y1[8] += a.y*xC.x;            \
    y0[9] += a.x*xC.y;  y1[9] += a.y*xC.y;            \
    y0[10]+= a.x*xC.z;  y1[10]+= a.y*xC.z;            \
    y0[11]+= a.x*xC.w;  y1[11]+= a.y*xC.w;            \
    y0[12]+= a.x*xD.x;  y1[12]+= a.y*xD.x;            \
    y0[13]+= a.x*xD.y;  y1[13]+= a.y*xD.y;            \
    y0[14]+= a.x*xD.z;  y1[14]+= a.y*xD.z;            \
    y0[15]+= a.x*xD.w;  y1[15]+= a.y*xD.w;

// ---------------------------------------------------------------------------
// K-1: prep — interleave all conv weights into global float2 buffers
// ---------------------------------------------------------------------------
__global__ __launch_bounds__(256) void k_prep(
    const float* __restrict__ rw1, const float* __restrict__ rw2,
    const float* __restrict__ fw1, const float* __restrict__ fw2,
    const float* __restrict__ ow1, const float* __restrict__ ow2)
{
    int i = blockIdx.x * 256 + threadIdx.x;
    if (i < 2048) {
        int c = i >> 5, l = i & 31;
        g_w1r[i] = make_float2(rw1[l*64 + c], rw1[(l+32)*64 + c]);
        g_w2r[i] = make_float2(rw2[l*64 + c], rw2[(l+32)*64 + c]);
        g_w1o[i] = make_float2(ow1[l*64 + c], ow1[(l+32)*64 + c]);
        g_w2o[i] = make_float2(ow2[l*64 + c], ow2[(l+32)*64 + c]);
    }
    if (i < 113*32) {
        int j = i >> 5, l = i & 31;
        g_w1f[i] = make_float2((l    < N2) ? fw1[l*113 + j]      : 0.f,
                               (l+32 < N2) ? fw1[(l+32)*113 + j] : 0.f);
    }
    if (i < 49*32) {
        int j = i >> 5, l = i & 31;
        g_w2f[i] = make_float2((l    < N2) ? fw2[l*49 + j]      : 0.f,
                               (l+32 < N2) ? fw2[(l+32)*49 + j] : 0.f);
    }
}

// ---------------------------------------------------------------------------
// K0: transpose semantic input [B,C,HW] -> [B*HW, C]   (spatial no longer needed)
// ---------------------------------------------------------------------------
__global__ __launch_bounds__(256) void k_transpose(const float* __restrict__ sem)
{
    __shared__ float t1[32][33];
    int b  = blockIdx.z;
    int c0 = blockIdx.y * 32;
    int p0 = blockIdx.x * 32;
    int tx = threadIdx.x, ty = threadIdx.y;
    #pragma unroll
    for (int i = ty; i < 32; i += 8)
        t1[i][tx] = sem[(b*CC + c0 + i)*HWP + p0 + tx];
    __syncthreads();
    #pragma unroll
    for (int i = ty; i < 32; i += 8)
        g_sem_t[(b*HWP + p0 + i)*CC + c0 + tx] = t1[tx][i];
}

// ---------------------------------------------------------------------------
// K1: range_proj. 16 px/warp, 32 accumulators, weights via LDG.
// ---------------------------------------------------------------------------
__global__ __launch_bounds__(128, 7) void k_range(
    const float* __restrict__ b1, const float* __restrict__ g,
    const float* __restrict__ be, const float* __restrict__ b2)
{
    extern __shared__ float sm[];
    float* xs = sm;                          // [4 warps][64 rows][16 px]
    int tid = threadIdx.x, lane = tid & 31, w = tid >> 5;

    float b1_0 = b1[lane], b1_1 = b1[lane+32];
    float g_0  = g[lane],  g_1  = g[lane+32];
    float be_0 = be[lane], be_1 = be[lane+32];
    float b2_0 = b2[lane], b2_1 = b2[lane+32];

    int pbase = blockIdx.x * 64 + w * 16;
    float* xw = xs + w * 1024;

    {
        int q = lane & 15, half = lane >> 4;
        const float* semp = g_sem_t + (pbase + q)*CC;
        int c0 = half * 32;
        for (int i = 0; i < 32; i++) {
            int ii = half ? (i ^ 1) : i;
            int c = c0 + ii;
            xw[c*16 + q] = semp[c];
        }
    }
    __syncwarp();

    float y0[16], y1[16];
    #pragma unroll
    for (int q = 0; q < 16; q++) { y0[q] = b1_0; y1[q] = b1_1; }

    #pragma unroll 2
    for (int c = 0; c < 64; c++) {
        float2 a = __ldg(&g_w1r[c*32 + lane]);
        float4 xA = *(const float4*)(xw + c*16);
        float4 xB = *(const float4*)(xw + c*16 + 4);
        float4 xC = *(const float4*)(xw + c*16 + 8);
        float4 xD = *(const float4*)(xw + c*16 + 12);
        ACC32(a, xA, xB, xC, xD)
    }

    {
        float h0[16], h1[16];
        #pragma unroll
        for (int q = 0; q < 16; q++) {
            float s = y0[q] + y1[q];
            float t = y0[q]*y0[q] + y1[q]*y1[q];
            #pragma unroll
            for (int o = 16; o; o >>= 1) {
                s += __shfl_xor_sync(0xffffffffu, s, o);
                t += __shfl_xor_sync(0xffffffffu, t, o);
            }
            float mean = s * (1.f/64.f);
            float rstd = rsqrtf(t * (1.f/64.f) - mean*mean + 1e-6f);
            float a0 = g_0 * (y0[q]-mean) * rstd + be_0;
            float a1 = g_1 * (y1[q]-mean) * rstd + be_1;
            h0[q] = a0 / (1.f + __expf(-a0));
            h1[q] = a1 / (1.f + __expf(-a1));
        }
        __syncwarp();
        *(float4*)&xw[lane*16]          = make_float4(h0[0],h0[1],h0[2],h0[3]);
        *(float4*)&xw[lane*16 + 4]      = make_float4(h0[4],h0[5],h0[6],h0[7]);
        *(float4*)&xw[lane*16 + 8]      = make_float4(h0[8],h0[9],h0[10],h0[11]);
        *(float4*)&xw[lane*16 + 12]     = make_float4(h0[12],h0[13],h0[14],h0[15]);
        *(float4*)&xw[(lane+32)*16]     = make_float4(h1[0],h1[1],h1[2],h1[3]);
        *(float4*)&xw[(lane+32)*16 + 4] = make_float4(h1[4],h1[5],h1[6],h1[7]);
        *(float4*)&xw[(lane+32)*16 + 8] = make_float4(h1[8],h1[9],h1[10],h1[11]);
        *(float4*)&xw[(lane+32)*16 +12] = make_float4(h1[12],h1[13],h1[14],h1[15]);
        __syncwarp();
    }

    #pragma unroll
    for (int q = 0; q < 16; q++) { y0[q] = b2_0; y1[q] = b2_1; }
    #pragma unroll 2
    for (int c = 0; c < 64; c++) {
        float2 a = __ldg(&g_w2r[c*32 + lane]);
        float4 xA = *(const float4*)(xw + c*16);
        float4 xB = *(const float4*)(xw + c*16 + 4);
        float4 xC = *(const float4*)(xw + c*16 + 8);
        float4 xD = *(const float4*)(xw + c*16 + 12);
        ACC32(a, xA, xB, xC, xD)
    }

    float* nrw = g_nrm_raw + PADF;
    #pragma unroll
    for (int q = 0; q < 16; q++) {
        float t = y0[q]*y0[q] + y1[q]*y1[q];
        #pragma unroll
        for (int o = 16; o; o >>= 1) t += __shfl_xor_sync(0xffffffffu, t, o);
        if (lane == 0) nrw[pbase + q] = t;
    }
    {
        float* pxw = g_px_raw + PADF;
        int b = pbase / HWP, pp = pbase % HWP;
        float* d0 = &pxw[(size_t)(b*CC + lane)*HWP + pp];
        *(float4*)d0        = make_float4(y0[0],y0[1],y0[2],y0[3]);
        *(float4*)(d0 + 4)  = make_float4(y0[4],y0[5],y0[6],y0[7]);
        *(float4*)(d0 + 8)  = make_float4(y0[8],y0[9],y0[10],y0[11]);
        *(float4*)(d0 + 12) = make_float4(y0[12],y0[13],y0[14],y0[15]);
        float* d1 = &pxw[(size_t)(b*CC + lane + 32)*HWP + pp];
        *(float4*)d1        = make_float4(y1[0],y1[1],y1[2],y1[3]);
        *(float4*)(d1 + 4)  = make_float4(y1[4],y1[5],y1[6],y1[7]);
        *(float4*)(d1 + 8)  = make_float4(y1[8],y1[9],y1[10],y1[11]);
        *(float4*)(d1 + 12) = make_float4(y1[12],y1[13],y1[14],y1[15]);
    }
}

// ---------------------------------------------------------------------------
// K2: bilateral v2 — register sliding window. Warp = (128 px, dy); lane = 4 px.
// Per channel: 4 LDG.128, 28 FMA, static window indices. No shuffles.
// ---------------------------------------------------------------------------
__global__ __launch_bounds__(224) void k_bilateral(const float* __restrict__ sigma)
{
    const float* px  = g_px_raw + PADF;
    const float* nrm = g_nrm_raw + PADF;
    int lane = threadIdx.x & 31, w = threadIdx.x >> 5;   // w = dyi (0..6)
    int dy   = w - 3;
    int pb   = blockIdx.x * 128;
    int b    = pb / HWP, ppb = pb % HWP;
    int l4   = lane << 2;
    int roff = dy * WW;

    float acc[7][4];
    #pragma unroll
    for (int i = 0; i < 7; i++)
        #pragma unroll
        for (int q = 0; q < 4; q++) acc[i][q] = 0.f;

    const float* cb = px + (size_t)b*(CC*HWP) + ppb + l4;
    #pragma unroll 2
    for (int c = 0; c < CC; c++) {
        const float* rc = cb + c*HWP;
        float4 cv = *(const float4*)rc;
        float4 wm = *(const float4*)(rc + roff - 4);
        float4 w0 = *(const float4*)(rc + roff);
        float4 wp = *(const float4*)(rc + roff + 4);
        float win[12] = {wm.x,wm.y,wm.z,wm.w, w0.x,w0.y,w0.z,w0.w, wp.x,wp.y,wp.z,wp.w};
        float cva[4]  = {cv.x, cv.y, cv.z, cv.w};
        #pragma unroll
        for (int i = 0; i < 7; i++)
            #pragma unroll
            for (int q = 0; q < 4; q++)
                acc[i][q] += cva[q] * win[q + i + 1];
    }

    float sg  = *sigma;
    float is2 = 0.5f / (sg*sg);
    const float* nb = nrm + pb + l4;
    float4 ncv = *(const float4*)nb;
    float4 nm  = *(const float4*)(nb + roff - 4);
    float4 n0  = *(const float4*)(nb + roff);
    float4 np  = *(const float4*)(nb + roff + 4);
    float nwin[12] = {nm.x,nm.y,nm.z,nm.w, n0.x,n0.y,n0.z,n0.w, np.x,np.y,np.z,np.w};
    float nca[4]   = {ncv.x, ncv.y, ncv.z, ncv.w};
    float dy2 = (float)(dy*dy);

    #pragma unroll
    for (int q = 0; q < 4; q++) {
        int ppl = ppb + l4 + q;
        int yy  = ppl / WW;
        int xx  = ppl - yy*WW;
        bool rok = ((unsigned)(yy + dy) < HH);
        float* op = &g_comb[(size_t)(pb + l4 + q)*N2 + w*7];
        #pragma unroll
        for (int i = 0; i < 7; i++) {
            int dx = i - 3;
            float d2 = fmaxf(nwin[q+i+1] + nca[q] - 2.f*acc[i][q], 0.f);
            float r  = __expf(-d2*(1.f/128.f) - (dy2 + (float)(dx*dx))*is2);
            bool ok  = rok && ((unsigned)(xx + dx) < WW);
            op[i] = ok ? r : 0.f;
        }
    }
}

// ---------------------------------------------------------------------------
// K3a: fixup. 16 px/warp, 32 accumulators, weights via LDG. (unchanged)
// ---------------------------------------------------------------------------
__global__ __launch_bounds__(128, 6) void k_fixup(
    const float* __restrict__ b1, const float* __restrict__ g,
    const float* __restrict__ be, const float* __restrict__ b2)
{
    extern __shared__ float sm[];
    float* xs = sm;                          // [4 warps][113][16]
    int tid = threadIdx.x, lane = tid & 31, w = tid >> 5;

    const bool has2 = (lane + 32) < N2;
    float b1_0 = (lane < N2) ? b1[lane] : 0.f;
    float b1_1 = has2 ? b1[lane+32] : 0.f;
    float g_0  = (lane < N2) ? g[lane]  : 0.f;
    float g_1  = has2 ? g[lane+32]  : 0.f;
    float be_0 = (lane < N2) ? be[lane] : 0.f;
    float be_1 = has2 ? be[lane+32] : 0.f;
    float b2_0 = (lane < N2) ? b2[lane] : 0.f;
    float b2_1 = has2 ? b2[lane+32] : 0.f;

    int pbase = blockIdx.x * 64 + w * 16;
    float* xw = xs + w * 1808;

    {
        int q = lane & 15, half = lane >> 4;
        int p = pbase + q;
        const float* combp = g_comb + (size_t)p*N2;
        const float* semp  = g_sem_t + (size_t)p*CC;
        if (half == 0) {
            for (int j = 0; j < 57; j++) {
                float v = (j < N2) ? combp[j] : semp[j - N2];
                xw[j*16 + q] = v;
            }
        } else {
            for (int j = 57; j < 113; j++)
                xw[j*16 + q] = semp[j - N2];
        }
    }
    __syncwarp();

    float y0[16], y1[16];
    #pragma unroll
    for (int q = 0; q < 16; q++) { y0[q] = b1_0; y1[q] = b1_1; }

    #pragma unroll 2
    for (int j = 0; j < 113; j++) {
        float2 a = __ldg(&g_w1f[j*32 + lane]);
        float4 xA = *(const float4*)(xw + j*16);
        float4 xB = *(const float4*)(xw + j*16 + 4);
        float4 xC = *(const float4*)(xw + j*16 + 8);
        float4 xD = *(const float4*)(xw + j*16 + 12);
        ACC32(a, xA, xB, xC, xD)
    }

    {
        float h0[16], h1[16];
        #pragma unroll
        for (int q = 0; q < 16; q++) {
            float s = y0[q] + (has2 ? y1[q] : 0.f);
            float t = y0[q]*y0[q] + (has2 ? y1[q]*y1[q] : 0.f);
            #pragma unroll
            for (int o = 16; o; o >>= 1) {
                s += __shfl_xor_sync(0xffffffffu, s, o);
                t += __shfl_xor_sync(0xffffffffu, t, o);
            }
            float mean = s * (1.f/49.f);
            float rstd = rsqrtf(t * (1.f/49.f) - mean*mean + 1e-6f);
            float a0 = g_0 * (y0[q]-mean) * rstd + be_0;
            float a1 = g_1 * (y1[q]-mean) * rstd + be_1;
            h0[q] = a0 / (1.f + __expf(-a0));
            h1[q] = a1 / (1.f + __expf(-a1));
        }
        __syncwarp();
        *(float4*)&xw[lane*16]      = make_float4(h0[0],h0[1],h0[2],h0[3]);
        *(float4*)&xw[lane*16 + 4]  = make_float4(h0[4],h0[5],h0[6],h0[7]);
        *(float4*)&xw[lane*16 + 8]  = make_float4(h0[8],h0[9],h0[10],h0[11]);
        *(float4*)&xw[lane*16 + 12] = make_float4(h0[12],h0[13],h0[14],h0[15]);
        if (has2) {
            *(float4*)&xw[(lane+32)*16]      = make_float4(h1[0],h1[1],h1[2],h1[3]);
            *(float4*)&xw[(lane+32)*16 + 4]  = make_float4(h1[4],h1[5],h1[6],h1[7]);
            *(float4*)&xw[(lane+32)*16 + 8]  = make_float4(h1[8],h1[9],h1[10],h1[11]);
            *(float4*)&xw[(lane+32)*16 +12]  = make_float4(h1[12],h1[13],h1[14],h1[15]);
        }
        __syncwarp();
    }

    #pragma unroll
    for (int q = 0; q < 16; q++) { y0[q] = b2_0; y1[q] = b2_1; }
    #pragma unroll 2
    for (int j = 0; j < 49; j++) {
        float2 a = __ldg(&g_w2f[j*32 + lane]);
        float4 xA = *(const float4*)(xw + j*16);
        float4 xB = *(const float4*)(xw + j*16 + 4);
        float4 xC = *(const float4*)(xw + j*16 + 8);
        float4 xD = *(const float4*)(xw + j*16 + 12);
        ACC32(a, xA, xB, xC, xD)
    }

    #pragma unroll
    for (int q = 0; q < 16; q++) {
        int p = pbase + q;
        float cb0 = g_comb[(size_t)p*N2 + lane];
        float cb1 = has2 ? g_comb[(size_t)p*N2 + lane + 32] : 0.f;
        float wv0 = cb0 * (1.f + 1.f/(1.f + __expf(-y0[q])));
        float wv1 = has2 ? cb1 * (1.f + 1.f/(1.f + __expf(-y1[q]))) : 0.f;
        float ss = wv0 + wv1;
        #pragma unroll
        for (int o = 16; o; o >>= 1) ss += __shfl_xor_sync(0xffffffffu, ss, o);
        float inv = 1.f / (ss + 1e-7f);
        g_comb[(size_t)p*N2 + lane] = wv0 * inv;
        if (has2) g_comb[(size_t)p*N2 + lane + 32] = wv1 * inv;
    }
}

// ---------------------------------------------------------------------------
// K4a: gather — channel-major window gather, reads ORIGINAL spatial input.
// Block = 128 px; warp handles 8 channels; comb staged transposed in smem;
// result transposed in-block to pixel-major g_gath.
// ---------------------------------------------------------------------------
__global__ __launch_bounds__(256, 3) void k_gather(const float* __restrict__ spa)
{
    extern __shared__ float sg_[];
    float* wsm  = sg_;              // [49][132] comb weights, pixel-minor
    float* tile = sg_ + 49*132;     // [128][65] gathered, for transpose
    int tid = threadIdx.x, lane = tid & 31, w = tid >> 5;
    int pb = blockIdx.x * 128;
    int b = pb / HWP, ppb = pb % HWP;
    int l4 = lane << 2;

    for (int idx = tid; idx < 128*N2; idx += 256) {
        int n = idx >> 7, p = idx & 127;
        wsm[n*132 + p] = g_comb[(size_t)(pb + p)*N2 + n];
    }
    __syncthreads();

    const int LIM = NPIX*CC - 4;
    int cbase0 = b*(CC*HWP) + ppb + l4;
    for (int k = 0; k < 8; k++) {
        int c = w + (k << 3);
        int base = cbase0 + c*HWP;
        float a0 = 0.f, a1 = 0.f, a2 = 0.f, a3 = 0.f;
        #pragma unroll
        for (int dyi = 0; dyi < 7; dyi++) {
            int ro = base + (dyi - 3)*WW;
            int im = min(max(ro - 4, 0), LIM);
            int i0 = min(max(ro,     0), LIM);
            int ip = min(max(ro + 4, 0), LIM);
            float4 wm = *(const float4*)(spa + im);
            float4 w0 = *(const float4*)(spa + i0);
            float4 wp = *(const float4*)(spa + ip);
            float win[12] = {wm.x,wm.y,wm.z,wm.w, w0.x,w0.y,w0.z,w0.w, wp.x,wp.y,wp.z,wp.w};
            #pragma unroll
            for (int i = 0; i < 7; i++) {
                float4 wv = *(const float4*)&wsm[(dyi*7 + i)*132 + l4];
                a0 += wv.x * win[i + 1];
                a1 += wv.y * win[i + 2];
                a2 += wv.z * win[i + 3];
                a3 += wv.w * win[i + 4];
            }
        }
        tile[(l4 + 0)*65 + c] = a0;
        tile[(l4 + 1)*65 + c] = a1;
        tile[(l4 + 2)*65 + c] = a2;
        tile[(l4 + 3)*65 + c] = a3;
    }
    __syncthreads();

    for (int idx = tid; idx < 128*CC; idx += 256) {
        int p = idx >> 6, c = idx & 63;
        g_gath[(size_t)(pb + p)*CC + c] = tile[p*65 + c];
    }
}

// ---------------------------------------------------------------------------
// K4b: output projection: conv -> LN -> conv from g_gath (pixel-major).
// Same structure as k_range (16 px/warp), no SiLU, final store channel-major.
// ---------------------------------------------------------------------------
__global__ __launch_bounds__(128, 7) void k_outproj(
    const float* __restrict__ b1, const float* __restrict__ g,
    const float* __restrict__ be, const float* __restrict__ b2,
    float* __restrict__ out)
{
    extern __shared__ float sm[];
    float* xs = sm;                          // [4 warps][64 rows][16 px]
    int tid = threadIdx.x, lane = tid & 31, w = tid >> 5;

    float b1_0 = b1[lane], b1_1 = b1[lane+32];
    float g_0  = g[lane],  g_1  = g[lane+32];
    float be_0 = be[lane], be_1 = be[lane+32];
    float b2_0 = b2[lane], b2_1 = b2[lane+32];

    int pbase = blockIdx.x * 64 + w * 16;
    float* xw = xs + w * 1024;

    {
        int q = lane & 15, half = lane >> 4;
        const float* gp = g_gath + (size_t)(pbase + q)*CC;
        int c0 = half * 32;
        for (int i = 0; i < 32; i++) {
            int ii = half ? (i ^ 1) : i;
            int c = c0 + ii;
            xw[c*16 + q] = gp[c];
        }
    }
    __syncwarp();

    float y0[16], y1[16];
    #pragma unroll
    for (int q = 0; q < 16; q++) { y0[q] = b1_0; y1[q] = b1_1; }

    #pragma unroll 2
    for (int c = 0; c < 64; c++) {
        float2 a = __ldg(&g_w1o[c*32 + lane]);
        float4 xA = *(const float4*)(xw + c*16);
        float4 xB = *(const float4*)(xw + c*16 + 4);
        float4 xC = *(const float4*)(xw + c*16 + 8);
        float4 xD = *(const float4*)(xw + c*16 + 12);
        ACC32(a, xA, xB, xC, xD)
    }

    // LN (no SiLU)
    {
        float h0[16], h1[16];
        #pragma unroll
        for (int q = 0; q < 16; q++) {
            float s = y0[q] + y1[q];
            float t = y0[q]*y0[q] + y1[q]*y1[q];
            #pragma unroll
            for (int o = 16; o; o >>= 1) {
                s += __shfl_xor_sync(0xffffffffu, s, o);
                t += __shfl_xor_sync(0xffffffffu, t, o);
            }
            float mean = s * (1.f/64.f);
            float rstd = rsqrtf(t * (1.f/64.f) - mean*mean + 1e-6f);
            h0[q] = g_0 * (y0[q]-mean) * rstd + be_0;
            h1[q] = g_1 * (y1[q]-mean) * rstd + be_1;
        }
        __syncwarp();
        *(float4*)&xw[lane*16]          = make_float4(h0[0],h0[1],h0[2],h0[3]);
        *(float4*)&xw[lane*16 + 4]      = make_float4(h0[4],h0[5],h0[6],h0[7]);
        *(float4*)&xw[lane*16 + 8]      = make_float4(h0[8],h0[9],h0[10],h0[11]);
        *(float4*)&xw[lane*16 + 12]     = make_float4(h0[12],h0[13],h0[14],h0[15]);
        *(float4*)&xw[(lane+32)*16]     = make_float4(h1[0],h1[1],h1[2],h1[3]);
        *(float4*)&xw[(lane+32)*16 + 4] = make_float4(h1[4],h1[5],h1[6],h1[7]);
        *(float4*)&xw[(lane+32)*16 + 8] = make_float4(h1[8],h1[9],h1[10],h1[11]);
        *(float4*)&xw[(lane+32)*16 +12] = make_float4(h1[12],h1[13],h1[14],h1[15]);
        __syncwarp();
    }

    #pragma unroll
    for (int q = 0; q < 16; q++) { y0[q] = b2_0; y1[q] = b2_1; }
    #pragma unroll 2
    for (int c = 0; c < 64; c++) {
        float2 a = __ldg(&g_w2o[c*32 + lane]);
        float4 xA = *(const float4*)(xw + c*16);
        float4 xB = *(const float4*)(xw + c*16 + 4);
        float4 xC = *(const float4*)(xw + c*16 + 8);
        float4 xD = *(const float4*)(xw + c*16 + 12);
        ACC32(a, xA, xB, xC, xD)
    }

    {
        int b = pbase / HWP, pp = pbase % HWP;
        float* d0 = &out[(size_t)(b*CC + lane)*HWP + pp];
        *(float4*)d0        = make_float4(y0[0],y0[1],y0[2],y0[3]);
        *(float4*)(d0 + 4)  = make_float4(y0[4],y0[5],y0[6],y0[7]);
        *(float4*)(d0 + 8)  = make_float4(y0[8],y0[9],y0[10],y0[11]);
        *(float4*)(d0 + 12) = make_float4(y0[12],y0[13],y0[14],y0[15]);
        float* d1 = &out[(size_t)(b*CC + lane + 32)*HWP + pp];
        *(float4*)d1        = make_float4(y1[0],y1[1],y1[2],y1[3]);
        *(float4*)(d1 + 4)  = make_float4(y1[4],y1[5],y1[6],y1[7]);
        *(float4*)(d1 + 8)  = make_float4(y1[8],y1[9],y1[10],y1[11]);
        *(float4*)(d1 + 12) = make_float4(y1[12],y1[13],y1[14],y1[15]);
    }
}

// ---------------------------------------------------------------------------
extern "C" void kernel_launch(void* const* d_in, const int* in_sizes, int n_in,
                              void* d_out, int out_size)
{
    const float* spa = (const float*)d_in[0];
    const float* sem = (const float*)d_in[1];

    static bool attr_set = false;
    if (!attr_set) {
        cudaFuncSetAttribute(k_range,   cudaFuncAttributeMaxDynamicSharedMemorySize, 16384);
        cudaFuncSetAttribute(k_fixup,   cudaFuncAttributeMaxDynamicSharedMemorySize, 28928);
        cudaFuncSetAttribute(k_gather,  cudaFuncAttributeMaxDynamicSharedMemorySize, 59152);
        cudaFuncSetAttribute(k_outproj, cudaFuncAttributeMaxDynamicSharedMemorySize, 16384);
        attr_set = true;
    }

    k_prep<<<15, 256>>>((const float*)d_in[2], (const float*)d_in[6],
                        (const float*)d_in[8], (const float*)d_in[12],
                        (const float*)d_in[14], (const float*)d_in[18]);

    dim3 tg(HWP/32, CC/32, BB), tb(32, 8);
    k_transpose<<<tg, tb>>>(sem);

    k_range<<<NPIX/64, 128, 16384>>>((const float*)d_in[3],
                                     (const float*)d_in[4], (const float*)d_in[5],
                                     (const float*)d_in[7]);

    k_bilateral<<<NPIX/128, 224>>>((const float*)d_in[20]);

    k_fixup<<<NPIX/64, 128, 28928>>>((const float*)d_in[9],
                                     (const float*)d_in[10], (const float*)d_in[11],
                                     (const float*)d_in[13]);

    k_gather<<<NPIX/128, 256, 59152>>>(spa);

    k_outproj<<<NPIX/64, 128, 16384>>>((const float*)d_in[15],
                                       (const float*)d_in[16], (const float*)d_in[17],
                                       (const float*)d_in[19],
                                       (float*)d_out);
}

// round 13
// speedup vs baseline: 1.2114x; 1.2114x over previous
#include <cuda_runtime.h>

// ---------------------------------------------------------------------------
// SpatialRangeAttention — GB300 sm_103a
// ---------------------------------------------------------------------------

#define BB   2
#define CC   64
#define HH   112
#define WW   112
#define HWP  (HH*WW)      // 12544
#define NPIX (BB*HWP)     // 25088
#define N2   49
#define PADF 512

// Scratch
__device__ float g_sem_t[NPIX*CC];              // semantic transposed [pix][c]
__device__ float g_spa_t[NPIX*CC];              // spatial  transposed [pix][c]
__device__ float g_px_raw[NPIX*CC + 2*PADF];    // range-proj, channel-major, padded
__device__ float g_nrm_raw[NPIX + 2*PADF];      // per-pixel ||px||^2, padded
__device__ float g_comb[NPIX*N2];               // bilateral / final weights [pix][n]

// Interleaved weight buffers (shared by all blocks; L1/L2-resident)
__device__ float2 g_w1r[64*32], g_w2r[64*32];   // range
__device__ float2 g_w1f[113*32], g_w2f[49*32];  // fixup (zero-padded o>=49)
__device__ float2 g_w1o[64*32], g_w2o[64*32];   // output

// 32-FMA block: weight pair a=(w[o],w[o+32]) times 16 pixel x-values
#define ACC32(a, xA, xB, xC, xD)                      \
    y0[0] += a.x*xA.x;  y1[0] += a.y*xA.x;            \
    y0[1] += a.x*xA.y;  y1[1] += a.y*xA.y;            \
    y0[2] += a.x*xA.z;  y1[2] += a.y*xA.z;            \
    y0[3] += a.x*xA.w;  y1[3] += a.y*xA.w;            \
    y0[4] += a.x*xB.x;  y1[4] += a.y*xB.x;            \
    y0[5] += a.x*xB.y;  y1[5] += a.y*xB.y;            \
    y0[6] += a.x*xB.z;  y1[6] += a.y*xB.z;            \
    y0[7] += a.x*xB.w;  y1[7] += a.y*xB.w;            \
    y0[8] += a.x*xC.x;  y1[8] += a.y*xC.x;            \
    y0[9] += a.x*xC.y;  y1[9] += a.y*xC.y;            \
    y0[10]+= a.x*xC.z;  y1[10]+= a.y*xC.z;            \
    y0[11]+= a.x*xC.w;  y1[11]+= a.y*xC.w;            \
    y0[12]+= a.x*xD.x;  y1[12]+= a.y*xD.x;            \
    y0[13]+= a.x*xD.y;  y1[13]+= a.y*xD.y;            \
    y0[14]+= a.x*xD.z;  y1[14]+= a.y*xD.z;            \
    y0[15]+= a.x*xD.w;  y1[15]+= a.y*xD.w;

// ---------------------------------------------------------------------------
// K-1: prep — interleave all conv weights into global float2 buffers
// ---------------------------------------------------------------------------
__global__ __launch_bounds__(256) void k_prep(
    const float* __restrict__ rw1, const float* __restrict__ rw2,
    const float* __restrict__ fw1, const float* __restrict__ fw2,
    const float* __restrict__ ow1, const float* __restrict__ ow2)
{
    int i = blockIdx.x * 256 + threadIdx.x;
    if (i < 2048) {
        int c = i >> 5, l = i & 31;
        g_w1r[i] = make_float2(rw1[l*64 + c], rw1[(l+32)*64 + c]);
        g_w2r[i] = make_float2(rw2[l*64 + c], rw2[(l+32)*64 + c]);
        g_w1o[i] = make_float2(ow1[l*64 + c], ow1[(l+32)*64 + c]);
        g_w2o[i] = make_float2(ow2[l*64 + c], ow2[(l+32)*64 + c]);
    }
    if (i < 113*32) {
        int j = i >> 5, l = i & 31;
        g_w1f[i] = make_float2((l    < N2) ? fw1[l*113 + j]      : 0.f,
                               (l+32 < N2) ? fw1[(l+32)*113 + j] : 0.f);
    }
    if (i < 49*32) {
        int j = i >> 5, l = i & 31;
        g_w2f[i] = make_float2((l    < N2) ? fw2[l*49 + j]      : 0.f,
                               (l+32 < N2) ? fw2[(l+32)*49 + j] : 0.f);
    }
}

// ---------------------------------------------------------------------------
// K0: transpose both inputs [B,C,HW] -> [B*HW, C]
// ---------------------------------------------------------------------------
__global__ __launch_bounds__(256) void k_transpose2(
    const float* __restrict__ sem, const float* __restrict__ spa)
{
    __shared__ float t1[32][33];
    __shared__ float t2[32][33];
    int b  = blockIdx.z;
    int c0 = blockIdx.y * 32;
    int p0 = blockIdx.x * 32;
    int tx = threadIdx.x, ty = threadIdx.y;
    #pragma unroll
    for (int i = ty; i < 32; i += 8) {
        int c = c0 + i, p = p0 + tx;
        t1[i][tx] = sem[(b*CC + c)*HWP + p];
        t2[i][tx] = spa[(b*CC + c)*HWP + p];
    }
    __syncthreads();
    #pragma unroll
    for (int i = ty; i < 32; i += 8) {
        int p = p0 + i, c = c0 + tx;
        g_sem_t[(b*HWP + p)*CC + c] = t1[tx][i];
        g_spa_t[(b*HWP + p)*CC + c] = t2[tx][i];
    }
}

// ---------------------------------------------------------------------------
// K1: range_proj. 16 px/warp, 32 accumulators, weights via LDG.
// ---------------------------------------------------------------------------
__global__ __launch_bounds__(128, 7) void k_range(
    const float* __restrict__ b1, const float* __restrict__ g,
    const float* __restrict__ be, const float* __restrict__ b2)
{
    extern __shared__ float sm[];
    float* xs = sm;                          // [4 warps][64 rows][16 px]
    int tid = threadIdx.x, lane = tid & 31, w = tid >> 5;

    float b1_0 = b1[lane], b1_1 = b1[lane+32];
    float g_0  = g[lane],  g_1  = g[lane+32];
    float be_0 = be[lane], be_1 = be[lane+32];
    float b2_0 = b2[lane], b2_1 = b2[lane+32];

    int pbase = blockIdx.x * 64 + w * 16;
    float* xw = xs + w * 1024;

    {
        int q = lane & 15, half = lane >> 4;
        const float* semp = g_sem_t + (pbase + q)*CC;
        int c0 = half * 32;
        for (int i = 0; i < 32; i++) {
            int ii = half ? (i ^ 1) : i;
            int c = c0 + ii;
            xw[c*16 + q] = semp[c];
        }
    }
    __syncwarp();

    float y0[16], y1[16];
    #pragma unroll
    for (int q = 0; q < 16; q++) { y0[q] = b1_0; y1[q] = b1_1; }

    #pragma unroll 2
    for (int c = 0; c < 64; c++) {
        float2 a = __ldg(&g_w1r[c*32 + lane]);
        float4 xA = *(const float4*)(xw + c*16);
        float4 xB = *(const float4*)(xw + c*16 + 4);
        float4 xC = *(const float4*)(xw + c*16 + 8);
        float4 xD = *(const float4*)(xw + c*16 + 12);
        ACC32(a, xA, xB, xC, xD)
    }

    {
        float h0[16], h1[16];
        #pragma unroll
        for (int q = 0; q < 16; q++) {
            float s = y0[q] + y1[q];
            float t = y0[q]*y0[q] + y1[q]*y1[q];
            #pragma unroll
            for (int o = 16; o; o >>= 1) {
                s += __shfl_xor_sync(0xffffffffu, s, o);
                t += __shfl_xor_sync(0xffffffffu, t, o);
            }
            float mean = s * (1.f/64.f);
            float rstd = rsqrtf(t * (1.f/64.f) - mean*mean + 1e-6f);
            float a0 = g_0 * (y0[q]-mean) * rstd + be_0;
            float a1 = g_1 * (y1[q]-mean) * rstd + be_1;
            h0[q] = a0 / (1.f + __expf(-a0));
            h1[q] = a1 / (1.f + __expf(-a1));
        }
        __syncwarp();
        *(float4*)&xw[lane*16]          = make_float4(h0[0],h0[1],h0[2],h0[3]);
        *(float4*)&xw[lane*16 + 4]      = make_float4(h0[4],h0[5],h0[6],h0[7]);
        *(float4*)&xw[lane*16 + 8]      = make_float4(h0[8],h0[9],h0[10],h0[11]);
        *(float4*)&xw[lane*16 + 12]     = make_float4(h0[12],h0[13],h0[14],h0[15]);
        *(float4*)&xw[(lane+32)*16]     = make_float4(h1[0],h1[1],h1[2],h1[3]);
        *(float4*)&xw[(lane+32)*16 + 4] = make_float4(h1[4],h1[5],h1[6],h1[7]);
        *(float4*)&xw[(lane+32)*16 + 8] = make_float4(h1[8],h1[9],h1[10],h1[11]);
        *(float4*)&xw[(lane+32)*16 +12] = make_float4(h1[12],h1[13],h1[14],h1[15]);
        __syncwarp();
    }

    #pragma unroll
    for (int q = 0; q < 16; q++) { y0[q] = b2_0; y1[q] = b2_1; }
    #pragma unroll 2
    for (int c = 0; c < 64; c++) {
        float2 a = __ldg(&g_w2r[c*32 + lane]);
        float4 xA = *(const float4*)(xw + c*16);
        float4 xB = *(const float4*)(xw + c*16 + 4);
        float4 xC = *(const float4*)(xw + c*16 + 8);
        float4 xD = *(const float4*)(xw + c*16 + 12);
        ACC32(a, xA, xB, xC, xD)
    }

    float* nrw = g_nrm_raw + PADF;
    #pragma unroll
    for (int q = 0; q < 16; q++) {
        float t = y0[q]*y0[q] + y1[q]*y1[q];
        #pragma unroll
        for (int o = 16; o; o >>= 1) t += __shfl_xor_sync(0xffffffffu, t, o);
        if (lane == 0) nrw[pbase + q] = t;
    }
    {
        float* pxw = g_px_raw + PADF;
        int b = pbase / HWP, pp = pbase % HWP;
        float* d0 = &pxw[(size_t)(b*CC + lane)*HWP + pp];
        *(float4*)d0        = make_float4(y0[0],y0[1],y0[2],y0[3]);
        *(float4*)(d0 + 4)  = make_float4(y0[4],y0[5],y0[6],y0[7]);
        *(float4*)(d0 + 8)  = make_float4(y0[8],y0[9],y0[10],y0[11]);
        *(float4*)(d0 + 12) = make_float4(y0[12],y0[13],y0[14],y0[15]);
        float* d1 = &pxw[(size_t)(b*CC + lane + 32)*HWP + pp];
        *(float4*)d1        = make_float4(y1[0],y1[1],y1[2],y1[3]);
        *(float4*)(d1 + 4)  = make_float4(y1[4],y1[5],y1[6],y1[7]);
        *(float4*)(d1 + 8)  = make_float4(y1[8],y1[9],y1[10],y1[11]);
        *(float4*)(d1 + 12) = make_float4(y1[12],y1[13],y1[14],y1[15]);
    }
}

// ---------------------------------------------------------------------------
// K2: bilateral v3b — register sliding window, warp = (64 px, dy), lane = 2 px.
// All window loads are float2 (8B-aligned: base even, roff even).
// Per channel: 1 LDG.64 center + 5 LDG.64 window + 14 FMA.
// ---------------------------------------------------------------------------
__global__ __launch_bounds__(256) void k_bilateral(const float* __restrict__ sigma)
{
    const float* px  = g_px_raw + PADF;
    const float* nrm = g_nrm_raw + PADF;
    int wid  = blockIdx.x * 8 + (threadIdx.x >> 5);
    int lane = threadIdx.x & 31;
    int gpix = wid / 7;
    int dyi  = wid - gpix*7;
    int dy   = dyi - 3;
    int pb   = gpix * 64;
    int b    = pb / HWP, ppb = pb % HWP;
    int l2   = lane << 1;
    int roff = dy * WW;

    float acc[7][2];
    #pragma unroll
    for (int i = 0; i < 7; i++) { acc[i][0] = 0.f; acc[i][1] = 0.f; }

    const float* cb = px + (size_t)b*(CC*HWP) + ppb + l2;
    #pragma unroll 4
    for (int c = 0; c < CC; c++) {
        const float* rc = cb + c*HWP;
        float2 cv = *(const float2*)rc;
        float2 w0 = *(const float2*)(rc + roff - 4);
        float2 w1 = *(const float2*)(rc + roff - 2);
        float2 w2 = *(const float2*)(rc + roff);
        float2 w3 = *(const float2*)(rc + roff + 2);
        float2 w4 = *(const float2*)(rc + roff + 4);
        float win[10] = {w0.x,w0.y, w1.x,w1.y, w2.x,w2.y, w3.x,w3.y, w4.x,w4.y};
        #pragma unroll
        for (int i = 0; i < 7; i++) {
            acc[i][0] += cv.x * win[i + 1];
            acc[i][1] += cv.y * win[i + 2];
        }
    }

    float sg  = *sigma;
    float is2 = 0.5f / (sg*sg);
    const float* nb = nrm + pb + l2;
    float2 ncv = *(const float2*)nb;
    float2 n0 = *(const float2*)(nb + roff - 4);
    float2 n1 = *(const float2*)(nb + roff - 2);
    float2 n2 = *(const float2*)(nb + roff);
    float2 n3 = *(const float2*)(nb + roff + 2);
    float2 n4 = *(const float2*)(nb + roff + 4);
    float nwin[10] = {n0.x,n0.y, n1.x,n1.y, n2.x,n2.y, n3.x,n3.y, n4.x,n4.y};
    float nca[2]   = {ncv.x, ncv.y};
    float dy2 = (float)(dy*dy);

    #pragma unroll
    for (int q = 0; q < 2; q++) {
        int ppl = ppb + l2 + q;
        int yy  = ppl / WW;
        int xx  = ppl - yy*WW;
        bool rok = ((unsigned)(yy + dy) < HH);
        float* op = &g_comb[(size_t)(pb + l2 + q)*N2 + dyi*7];
        #pragma unroll
        for (int i = 0; i < 7; i++) {
            int dx = i - 3;
            float d2 = fmaxf(nwin[q+i+1] + nca[q] - 2.f*acc[i][q], 0.f);
            float r  = __expf(-d2*(1.f/128.f) - (dy2 + (float)(dx*dx))*is2);
            bool ok  = rok && ((unsigned)(xx + dx) < WW);
            op[i] = ok ? r : 0.f;
        }
    }
}

// ---------------------------------------------------------------------------
// K3a: fixup. 16 px/warp, 32 accumulators, weights via LDG.
// ---------------------------------------------------------------------------
__global__ __launch_bounds__(128, 6) void k_fixup(
    const float* __restrict__ b1, const float* __restrict__ g,
    const float* __restrict__ be, const float* __restrict__ b2)
{
    extern __shared__ float sm[];
    float* xs = sm;                          // [4 warps][113][16]
    int tid = threadIdx.x, lane = tid & 31, w = tid >> 5;

    const bool has2 = (lane + 32) < N2;
    float b1_0 = (lane < N2) ? b1[lane] : 0.f;
    float b1_1 = has2 ? b1[lane+32] : 0.f;
    float g_0  = (lane < N2) ? g[lane]  : 0.f;
    float g_1  = has2 ? g[lane+32]  : 0.f;
    float be_0 = (lane < N2) ? be[lane] : 0.f;
    float be_1 = has2 ? be[lane+32] : 0.f;
    float b2_0 = (lane < N2) ? b2[lane] : 0.f;
    float b2_1 = has2 ? b2[lane+32] : 0.f;

    int pbase = blockIdx.x * 64 + w * 16;
    float* xw = xs + w * 1808;

    {
        int q = lane & 15, half = lane >> 4;
        int p = pbase + q;
        const float* combp = g_comb + (size_t)p*N2;
        const float* semp  = g_sem_t + (size_t)p*CC;
        if (half == 0) {
            for (int j = 0; j < 57; j++) {
                float v = (j < N2) ? combp[j] : semp[j - N2];
                xw[j*16 + q] = v;
            }
        } else {
            for (int j = 57; j < 113; j++)
                xw[j*16 + q] = semp[j - N2];
        }
    }
    __syncwarp();

    float y0[16], y1[16];
    #pragma unroll
    for (int q = 0; q < 16; q++) { y0[q] = b1_0; y1[q] = b1_1; }

    #pragma unroll 2
    for (int j = 0; j < 113; j++) {
        float2 a = __ldg(&g_w1f[j*32 + lane]);
        float4 xA = *(const float4*)(xw + j*16);
        float4 xB = *(const float4*)(xw + j*16 + 4);
        float4 xC = *(const float4*)(xw + j*16 + 8);
        float4 xD = *(const float4*)(xw + j*16 + 12);
        ACC32(a, xA, xB, xC, xD)
    }

    {
        float h0[16], h1[16];
        #pragma unroll
        for (int q = 0; q < 16; q++) {
            float s = y0[q] + (has2 ? y1[q] : 0.f);
            float t = y0[q]*y0[q] + (has2 ? y1[q]*y1[q] : 0.f);
            #pragma unroll
            for (int o = 16; o; o >>= 1) {
                s += __shfl_xor_sync(0xffffffffu, s, o);
                t += __shfl_xor_sync(0xffffffffu, t, o);
            }
            float mean = s * (1.f/49.f);
            float rstd = rsqrtf(t * (1.f/49.f) - mean*mean + 1e-6f);
            float a0 = g_0 * (y0[q]-mean) * rstd + be_0;
            float a1 = g_1 * (y1[q]-mean) * rstd + be_1;
            h0[q] = a0 / (1.f + __expf(-a0));
            h1[q] = a1 / (1.f + __expf(-a1));
        }
        __syncwarp();
        *(float4*)&xw[lane*16]      = make_float4(h0[0],h0[1],h0[2],h0[3]);
        *(float4*)&xw[lane*16 + 4]  = make_float4(h0[4],h0[5],h0[6],h0[7]);
        *(float4*)&xw[lane*16 + 8]  = make_float4(h0[8],h0[9],h0[10],h0[11]);
        *(float4*)&xw[lane*16 + 12] = make_float4(h0[12],h0[13],h0[14],h0[15]);
        if (has2) {
            *(float4*)&xw[(lane+32)*16]      = make_float4(h1[0],h1[1],h1[2],h1[3]);
            *(float4*)&xw[(lane+32)*16 + 4]  = make_float4(h1[4],h1[5],h1[6],h1[7]);
            *(float4*)&xw[(lane+32)*16 + 8]  = make_float4(h1[8],h1[9],h1[10],h1[11]);
            *(float4*)&xw[(lane+32)*16 +12]  = make_float4(h1[12],h1[13],h1[14],h1[15]);
        }
        __syncwarp();
    }

    #pragma unroll
    for (int q = 0; q < 16; q++) { y0[q] = b2_0; y1[q] = b2_1; }
    #pragma unroll 2
    for (int j = 0; j < 49; j++) {
        float2 a = __ldg(&g_w2f[j*32 + lane]);
        float4 xA = *(const float4*)(xw + j*16);
        float4 xB = *(const float4*)(xw + j*16 + 4);
        float4 xC = *(const float4*)(xw + j*16 + 8);
        float4 xD = *(const float4*)(xw + j*16 + 12);
        ACC32(a, xA, xB, xC, xD)
    }

    #pragma unroll
    for (int q = 0; q < 16; q++) {
        int p = pbase + q;
        float cb0 = g_comb[(size_t)p*N2 + lane];
        float cb1 = has2 ? g_comb[(size_t)p*N2 + lane + 32] : 0.f;
        float wv0 = cb0 * (1.f + 1.f/(1.f + __expf(-y0[q])));
        float wv1 = has2 ? cb1 * (1.f + 1.f/(1.f + __expf(-y1[q]))) : 0.f;
        float ss = wv0 + wv1;
        #pragma unroll
        for (int o = 16; o; o >>= 1) ss += __shfl_xor_sync(0xffffffffu, ss, o);
        float inv = 1.f / (ss + 1e-7f);
        g_comb[(size_t)p*N2 + lane] = wv0 * inv;
        if (has2) g_comb[(size_t)p*N2 + lane + 32] = wv1 * inv;
    }
}

// ---------------------------------------------------------------------------
// K3b: weighted neighborhood reduction + output_proj, weights via LDG.
// 8 px/warp; gather clamped predicate-free.
// ---------------------------------------------------------------------------
__global__ __launch_bounds__(256, 4) void k_output(
    const float* __restrict__ b1, const float* __restrict__ g,
    const float* __restrict__ be, const float* __restrict__ b2,
    float* __restrict__ out)
{
    extern __shared__ float sm[];
    float* wsb = sm;                        // [8][52]
    float* os  = sm + 416;                  // [8][64][8]
    int tid = threadIdx.x, lane = tid & 31, w = tid >> 5;

    float b1_0 = b1[lane], b1_1 = b1[lane+32];
    float g_0  = g[lane],  g_1  = g[lane+32];
    float be_0 = be[lane], be_1 = be[lane+32];
    float b2_0 = b2[lane], b2_1 = b2[lane+32];

    int pbase = blockIdx.x * 64 + w * 8;
    float* ow   = os  + w * 512;
    float* wrow = wsb + w * 52;

    {
        float a0[8], a1[8];
        for (int q = 0; q < 8; q++) {
            int p = pbase + q;
            int b = p / HWP, pp = p % HWP, yy = pp / WW, xx = pp % WW;

            for (int n = lane; n < N2; n += 32) wrow[n] = g_comb[(size_t)p*N2 + n];
            __syncwarp();

            float s0 = 0.f, s1 = 0.f;
            int n = 0;
            #pragma unroll
            for (int dy = -3; dy <= 3; dy++) {
                int ny = min(max(yy + dy, 0), HH-1);
                const float* rbase = &g_spa_t[(b*HWP + ny*WW)*CC + lane*2];
                #pragma unroll
                for (int dx = -3; dx <= 3; dx++, n++) {
                    int nx = min(max(xx + dx, 0), WW-1);
                    float wv = wrow[n];
                    float2 sv = *(const float2*)(rbase + nx*CC);
                    s0 += sv.x * wv;
                    s1 += sv.y * wv;
                }
            }
            a0[q] = s0; a1[q] = s1;
            __syncwarp();
        }
        *(float4*)&ow[(lane*2)*8]       = make_float4(a0[0],a0[1],a0[2],a0[3]);
        *(float4*)&ow[(lane*2)*8 + 4]   = make_float4(a0[4],a0[5],a0[6],a0[7]);
        *(float4*)&ow[(lane*2+1)*8]     = make_float4(a1[0],a1[1],a1[2],a1[3]);
        *(float4*)&ow[(lane*2+1)*8 + 4] = make_float4(a1[4],a1[5],a1[6],a1[7]);
        __syncwarp();
    }

    float y0[8], y1[8];
    #pragma unroll
    for (int q = 0; q < 8; q++) { y0[q] = b1_0; y1[q] = b1_1; }
    #pragma unroll 4
    for (int c = 0; c < 64; c++) {
        float2 a = __ldg(&g_w1o[c*32 + lane]);
        float4 xa = *(const float4*)(ow + c*8);
        float4 xb = *(const float4*)(ow + c*8 + 4);
        y0[0]+=a.x*xa.x; y1[0]+=a.y*xa.x;
        y0[1]+=a.x*xa.y; y1[1]+=a.y*xa.y;
        y0[2]+=a.x*xa.z; y1[2]+=a.y*xa.z;
        y0[3]+=a.x*xa.w; y1[3]+=a.y*xa.w;
        y0[4]+=a.x*xb.x; y1[4]+=a.y*xb.x;
        y0[5]+=a.x*xb.y; y1[5]+=a.y*xb.y;
        y0[6]+=a.x*xb.z; y1[6]+=a.y*xb.z;
        y0[7]+=a.x*xb.w; y1[7]+=a.y*xb.w;
    }

    {
        float h0[8], h1[8];
        #pragma unroll
        for (int q = 0; q < 8; q++) {
            float s = y0[q] + y1[q];
            float t = y0[q]*y0[q] + y1[q]*y1[q];
            #pragma unroll
            for (int o = 16; o; o >>= 1) {
                s += __shfl_xor_sync(0xffffffffu, s, o);
                t += __shfl_xor_sync(0xffffffffu, t, o);
            }
            float mean = s * (1.f/64.f);
            float rstd = rsqrtf(t * (1.f/64.f) - mean*mean + 1e-6f);
            h0[q] = g_0 * (y0[q]-mean) * rstd + be_0;
            h1[q] = g_1 * (y1[q]-mean) * rstd + be_1;
        }
        __syncwarp();
        *(float4*)&ow[lane*8]          = make_float4(h0[0],h0[1],h0[2],h0[3]);
        *(float4*)&ow[lane*8 + 4]      = make_float4(h0[4],h0[5],h0[6],h0[7]);
        *(float4*)&ow[(lane+32)*8]     = make_float4(h1[0],h1[1],h1[2],h1[3]);
        *(float4*)&ow[(lane+32)*8 + 4] = make_float4(h1[4],h1[5],h1[6],h1[7]);
        __syncwarp();
    }

    #pragma unroll
    for (int q = 0; q < 8; q++) { y0[q] = b2_0; y1[q] = b2_1; }
    #pragma unroll 4
    for (int c = 0; c < 64; c++) {
        float2 a = __ldg(&g_w2o[c*32 + lane]);
        float4 xa = *(const float4*)(ow + c*8);
        float4 xb = *(const float4*)(ow + c*8 + 4);
        y0[0]+=a.x*xa.x; y1[0]+=a.y*xa.x;
        y0[1]+=a.x*xa.y; y1[1]+=a.y*xa.y;
        y0[2]+=a.x*xa.z; y1[2]+=a.y*xa.z;
        y0[3]+=a.x*xa.w; y1[3]+=a.y*xa.w;
        y0[4]+=a.x*xb.x; y1[4]+=a.y*xb.x;
        y0[5]+=a.x*xb.y; y1[5]+=a.y*xb.y;
        y0[6]+=a.x*xb.z; y1[6]+=a.y*xb.z;
        y0[7]+=a.x*xb.w; y1[7]+=a.y*xb.w;
    }

    #pragma unroll
    for (int q = 0; q < 8; q++) {
        int p = pbase + q;
        int b = p / HWP, pp = p % HWP;
        out[(b*CC + lane)*HWP + pp]      = y0[q];
        out[(b*CC + lane + 32)*HWP + pp] = y1[q];
    }
}

// ---------------------------------------------------------------------------
extern "C" void kernel_launch(void* const* d_in, const int* in_sizes, int n_in,
                              void* d_out, int out_size)
{
    const float* spa = (const float*)d_in[0];
    const float* sem = (const float*)d_in[1];

    static bool attr_set = false;
    if (!attr_set) {
        cudaFuncSetAttribute(k_range,  cudaFuncAttributeMaxDynamicSharedMemorySize, 16384);
        cudaFuncSetAttribute(k_fixup,  cudaFuncAttributeMaxDynamicSharedMemorySize, 28928);
        cudaFuncSetAttribute(k_output, cudaFuncAttributeMaxDynamicSharedMemorySize, 18048);
        attr_set = true;
    }

    k_prep<<<15, 256>>>((const float*)d_in[2], (const float*)d_in[6],
                        (const float*)d_in[8], (const float*)d_in[12],
                        (const float*)d_in[14], (const float*)d_in[18]);

    dim3 tg(HWP/32, CC/32, BB), tb(32, 8);
    k_transpose2<<<tg, tb>>>(sem, spa);

    k_range<<<NPIX/64, 128, 16384>>>((const float*)d_in[3],
                                     (const float*)d_in[4], (const float*)d_in[5],
                                     (const float*)d_in[7]);

    // warps = (NPIX/64) * 7 = 2744 ; 8 warps/block -> 343 blocks
    k_bilateral<<<343, 256>>>((const float*)d_in[20]);

    k_fixup<<<NPIX/64, 128, 28928>>>((const float*)d_in[9],
                                     (const float*)d_in[10], (const float*)d_in[11],
                                     (const float*)d_in[13]);

    k_output<<<NPIX/64, 256, 18048>>>((const float*)d_in[15],
                                      (const float*)d_in[16], (const float*)d_in[17],
                                      (const float*)d_in[19],
                                      (float*)d_out);
}

// round 14
// speedup vs baseline: 1.2424x; 1.0256x over previous
#include <cuda_runtime.h>

// ---------------------------------------------------------------------------
// SpatialRangeAttention — GB300 sm_103a
// ---------------------------------------------------------------------------

#define BB   2
#define CC   64
#define HH   112
#define WW   112
#define HWP  (HH*WW)      // 12544
#define NPIX (BB*HWP)     // 25088
#define N2   49

// Scratch
__device__ float g_spa_t[NPIX*CC];   // spatial transposed [pix][c]
__device__ float g_px_cm[NPIX*CC];   // range-projected, CHANNEL-major [b][c][hw]
__device__ float g_nrm[NPIX];        // per-pixel ||px||^2
__device__ float g_comb[NPIX*N2];    // bilateral / final weights [pix][n]

// Interleaved weight buffers (shared by all blocks; L1/L2-resident)
__device__ float2 g_w1r[64*32], g_w2r[64*32];   // range
__device__ float2 g_w1f[113*32], g_w2f[49*32];  // fixup (zero-padded o>=49)
__device__ float2 g_w1o[64*32], g_w2o[64*32];   // output

// 32-FMA block: weight pair a=(w[o],w[o+32]) times 16 pixel x-values
#define ACC32(a, xA, xB, xC, xD)                      \
    y0[0] += a.x*xA.x;  y1[0] += a.y*xA.x;            \
    y0[1] += a.x*xA.y;  y1[1] += a.y*xA.y;            \
    y0[2] += a.x*xA.z;  y1[2] += a.y*xA.z;            \
    y0[3] += a.x*xA.w;  y1[3] += a.y*xA.w;            \
    y0[4] += a.x*xB.x;  y1[4] += a.y*xB.x;            \
    y0[5] += a.x*xB.y;  y1[5] += a.y*xB.y;            \
    y0[6] += a.x*xB.z;  y1[6] += a.y*xB.z;            \
    y0[7] += a.x*xB.w;  y1[7] += a.y*xB.w;            \
    y0[8] += a.x*xC.x;  y1[8] += a.y*xC.x;            \
    y0[9] += a.x*xC.y;  y1[9] += a.y*xC.y;            \
    y0[10]+= a.x*xC.z;  y1[10]+= a.y*xC.z;            \
    y0[11]+= a.x*xC.w;  y1[11]+= a.y*xC.w;            \
    y0[12]+= a.x*xD.x;  y1[12]+= a.y*xD.x;            \
    y0[13]+= a.x*xD.y;  y1[13]+= a.y*xD.y;            \
    y0[14]+= a.x*xD.z;  y1[14]+= a.y*xD.z;            \
    y0[15]+= a.x*xD.w;  y1[15]+= a.y*xD.w;

// ---------------------------------------------------------------------------
// K-1: prep — interleave all conv weights into global float2 buffers
// ---------------------------------------------------------------------------
__global__ __launch_bounds__(256) void k_prep(
    const float* __restrict__ rw1, const float* __restrict__ rw2,
    const float* __restrict__ fw1, const float* __restrict__ fw2,
    const float* __restrict__ ow1, const float* __restrict__ ow2)
{
    int i = blockIdx.x * 256 + threadIdx.x;
    if (i < 2048) {
        int c = i >> 5, l = i & 31;
        g_w1r[i] = make_float2(rw1[l*64 + c], rw1[(l+32)*64 + c]);
        g_w2r[i] = make_float2(rw2[l*64 + c], rw2[(l+32)*64 + c]);
        g_w1o[i] = make_float2(ow1[l*64 + c], ow1[(l+32)*64 + c]);
        g_w2o[i] = make_float2(ow2[l*64 + c], ow2[(l+32)*64 + c]);
    }
    if (i < 113*32) {
        int j = i >> 5, l = i & 31;
        g_w1f[i] = make_float2((l    < N2) ? fw1[l*113 + j]      : 0.f,
                               (l+32 < N2) ? fw1[(l+32)*113 + j] : 0.f);
    }
    if (i < 49*32) {
        int j = i >> 5, l = i & 31;
        g_w2f[i] = make_float2((l    < N2) ? fw2[l*49 + j]      : 0.f,
                               (l+32 < N2) ? fw2[(l+32)*49 + j] : 0.f);
    }
}

// ---------------------------------------------------------------------------
// K0: transpose spatial input [B,C,HW] -> [B*HW, C]  (sem read directly now)
// ---------------------------------------------------------------------------
__global__ __launch_bounds__(256) void k_transpose(const float* __restrict__ spa)
{
    __shared__ float t1[32][33];
    int b  = blockIdx.z;
    int c0 = blockIdx.y * 32;
    int p0 = blockIdx.x * 32;
    int tx = threadIdx.x, ty = threadIdx.y;
    #pragma unroll
    for (int i = ty; i < 32; i += 8)
        t1[i][tx] = spa[(b*CC + c0 + i)*HWP + p0 + tx];
    __syncthreads();
    #pragma unroll
    for (int i = ty; i < 32; i += 8)
        g_spa_t[(b*HWP + p0 + i)*CC + c0 + tx] = t1[tx][i];
}

// ---------------------------------------------------------------------------
// K1: range_proj. 16 px/warp, 32 accumulators, weights via LDG.
// Stages directly from channel-major sem input (coalesced 64B per c).
// ---------------------------------------------------------------------------
__global__ __launch_bounds__(128, 7) void k_range(
    const float* __restrict__ sem,
    const float* __restrict__ b1, const float* __restrict__ g,
    const float* __restrict__ be, const float* __restrict__ b2)
{
    extern __shared__ float sm[];
    float* xs = sm;                          // [4 warps][64 rows][16 px]
    int tid = threadIdx.x, lane = tid & 31, w = tid >> 5;

    float b1_0 = b1[lane], b1_1 = b1[lane+32];
    float g_0  = g[lane],  g_1  = g[lane+32];
    float be_0 = be[lane], be_1 = be[lane+32];
    float b2_0 = b2[lane], b2_1 = b2[lane+32];

    int pbase = blockIdx.x * 64 + w * 16;
    int bI = pbase / HWP, ppb = pbase % HWP;
    float* xw = xs + w * 1024;

    // stage 16 pixels from CHANNEL-MAJOR sem: lane q reads pixel ppb+q at
    // channel c -> 16 consecutive floats per (half, c) = coalesced.
    {
        int q = lane & 15, half = lane >> 4;
        const float* semb = sem + (size_t)bI*CC*HWP + ppb + q;
        int c0 = half * 32;
        #pragma unroll 4
        for (int i = 0; i < 32; i++) {
            int c = c0 + i;
            xw[c*16 + q] = semb[(size_t)c*HWP];
        }
    }
    __syncwarp();

    float y0[16], y1[16];
    #pragma unroll
    for (int q = 0; q < 16; q++) { y0[q] = b1_0; y1[q] = b1_1; }

    #pragma unroll 2
    for (int c = 0; c < 64; c++) {
        float2 a = __ldg(&g_w1r[c*32 + lane]);
        float4 xA = *(const float4*)(xw + c*16);
        float4 xB = *(const float4*)(xw + c*16 + 4);
        float4 xC = *(const float4*)(xw + c*16 + 8);
        float4 xD = *(const float4*)(xw + c*16 + 12);
        ACC32(a, xA, xB, xC, xD)
    }

    {
        float h0[16], h1[16];
        #pragma unroll
        for (int q = 0; q < 16; q++) {
            float s = y0[q] + y1[q];
            float t = y0[q]*y0[q] + y1[q]*y1[q];
            #pragma unroll
            for (int o = 16; o; o >>= 1) {
                s += __shfl_xor_sync(0xffffffffu, s, o);
                t += __shfl_xor_sync(0xffffffffu, t, o);
            }
            float mean = s * (1.f/64.f);
            float rstd = rsqrtf(t * (1.f/64.f) - mean*mean + 1e-6f);
            float a0 = g_0 * (y0[q]-mean) * rstd + be_0;
            float a1 = g_1 * (y1[q]-mean) * rstd + be_1;
            h0[q] = a0 / (1.f + __expf(-a0));
            h1[q] = a1 / (1.f + __expf(-a1));
        }
        __syncwarp();
        *(float4*)&xw[lane*16]          = make_float4(h0[0],h0[1],h0[2],h0[3]);
        *(float4*)&xw[lane*16 + 4]      = make_float4(h0[4],h0[5],h0[6],h0[7]);
        *(float4*)&xw[lane*16 + 8]      = make_float4(h0[8],h0[9],h0[10],h0[11]);
        *(float4*)&xw[lane*16 + 12]     = make_float4(h0[12],h0[13],h0[14],h0[15]);
        *(float4*)&xw[(lane+32)*16]     = make_float4(h1[0],h1[1],h1[2],h1[3]);
        *(float4*)&xw[(lane+32)*16 + 4] = make_float4(h1[4],h1[5],h1[6],h1[7]);
        *(float4*)&xw[(lane+32)*16 + 8] = make_float4(h1[8],h1[9],h1[10],h1[11]);
        *(float4*)&xw[(lane+32)*16 +12] = make_float4(h1[12],h1[13],h1[14],h1[15]);
        __syncwarp();
    }

    #pragma unroll
    for (int q = 0; q < 16; q++) { y0[q] = b2_0; y1[q] = b2_1; }
    #pragma unroll 2
    for (int c = 0; c < 64; c++) {
        float2 a = __ldg(&g_w2r[c*32 + lane]);
        float4 xA = *(const float4*)(xw + c*16);
        float4 xB = *(const float4*)(xw + c*16 + 4);
        float4 xC = *(const float4*)(xw + c*16 + 8);
        float4 xD = *(const float4*)(xw + c*16 + 12);
        ACC32(a, xA, xB, xC, xD)
    }

    // norms per pixel
    #pragma unroll
    for (int q = 0; q < 16; q++) {
        float t = y0[q]*y0[q] + y1[q]*y1[q];
        #pragma unroll
        for (int o = 16; o; o >>= 1) t += __shfl_xor_sync(0xffffffffu, t, o);
        if (lane == 0) g_nrm[pbase + q] = t;
    }
    // channel-major stores: 16 consecutive pixels -> 4x STG.128 per half
    {
        float* d0 = &g_px_cm[(size_t)(bI*CC + lane)*HWP + ppb];
        *(float4*)d0        = make_float4(y0[0],y0[1],y0[2],y0[3]);
        *(float4*)(d0 + 4)  = make_float4(y0[4],y0[5],y0[6],y0[7]);
        *(float4*)(d0 + 8)  = make_float4(y0[8],y0[9],y0[10],y0[11]);
        *(float4*)(d0 + 12) = make_float4(y0[12],y0[13],y0[14],y0[15]);
        float* d1 = &g_px_cm[(size_t)(bI*CC + lane + 32)*HWP + ppb];
        *(float4*)d1        = make_float4(y1[0],y1[1],y1[2],y1[3]);
        *(float4*)(d1 + 4)  = make_float4(y1[4],y1[5],y1[6],y1[7]);
        *(float4*)(d1 + 8)  = make_float4(y1[8],y1[9],y1[10],y1[11]);
        *(float4*)(d1 + 12) = make_float4(y1[12],y1[13],y1[14],y1[15]);
    }
}

// ---------------------------------------------------------------------------
// K2: bilateral (R9-exact): dist2 = |n|^2+|c|^2-2dot. Warp = (32 pixels, dy).
// ---------------------------------------------------------------------------
__global__ __launch_bounds__(256) void k_bilateral(const float* __restrict__ sigma)
{
    int wid  = (blockIdx.x << 3) + (threadIdx.x >> 5);
    int lane = threadIdx.x & 31;
    int gpix = wid / 7;
    int dyi  = wid - gpix*7;
    int dy   = dyi - 3;

    int p  = (gpix << 5) + lane;
    int b  = p / HWP, pp = p % HWP, yy = pp / WW, xx = pp % WW;
    int ny = yy + dy;
    bool rowok = ((unsigned)ny < HH);
    int nrow = (rowok ? ny : yy) * WW;

    const float* base = g_px_cm + (size_t)b * (CC*HWP);

    int off[7]; unsigned okm = 0;
    #pragma unroll
    for (int i = 0; i < 7; i++) {
        int nx = xx + i - 3;
        bool o = rowok & ((unsigned)nx < WW);
        okm |= (o ? 1u : 0u) << i;
        off[i] = nrow + (o ? nx : xx);
    }

    float acc[7] = {0.f,0.f,0.f,0.f,0.f,0.f,0.f};
    #pragma unroll 4
    for (int c = 0; c < CC; c++) {
        const float* rc = base + c*HWP;
        float cv = rc[pp];
        #pragma unroll
        for (int i = 0; i < 7; i++) acc[i] += cv * rc[off[i]];
    }

    float nc = g_nrm[p];
    float sg = *sigma;
    float is2 = 0.5f / (sg*sg);
    float* outp = &g_comb[(size_t)p*N2 + dyi*7];
    const float* nrmb = &g_nrm[b*HWP];
    #pragma unroll
    for (int i = 0; i < 7; i++) {
        float res = 0.f;
        if ((okm >> i) & 1u) {
            float d2 = fmaxf(nrmb[off[i]] + nc - 2.f*acc[i], 0.f);
            float fdx = (float)(i - 3);
            res = __expf(-d2*(1.f/128.f) - ((float)(dy*dy) + fdx*fdx)*is2);
        }
        outp[i] = res;
    }
}

// ---------------------------------------------------------------------------
// K3a: fixup. 16 px/warp, 32 accumulators, weights via LDG.
// Sem part staged directly from channel-major sem (coalesced).
// ---------------------------------------------------------------------------
__global__ __launch_bounds__(128, 6) void k_fixup(
    const float* __restrict__ sem,
    const float* __restrict__ b1, const float* __restrict__ g,
    const float* __restrict__ be, const float* __restrict__ b2)
{
    extern __shared__ float sm[];
    float* xs = sm;                          // [4 warps][113][16]
    int tid = threadIdx.x, lane = tid & 31, w = tid >> 5;

    const bool has2 = (lane + 32) < N2;
    float b1_0 = (lane < N2) ? b1[lane] : 0.f;
    float b1_1 = has2 ? b1[lane+32] : 0.f;
    float g_0  = (lane < N2) ? g[lane]  : 0.f;
    float g_1  = has2 ? g[lane+32]  : 0.f;
    float be_0 = (lane < N2) ? be[lane] : 0.f;
    float be_1 = has2 ? be[lane+32] : 0.f;
    float b2_0 = (lane < N2) ? b2[lane] : 0.f;
    float b2_1 = has2 ? b2[lane+32] : 0.f;

    int pbase = blockIdx.x * 64 + w * 16;
    int bI = pbase / HWP, ppb = pbase % HWP;
    float* xw = xs + w * 1808;

    // stage: comb (49) from pixel-major comb; sem (64) from channel-major input
    {
        int q = lane & 15, half = lane >> 4;
        const float* semb = sem + (size_t)bI*CC*HWP + ppb + q;
        if (half == 0) {
            const float* combp = g_comb + (size_t)(pbase + q)*N2;
            for (int j = 0; j < 49; j++)
                xw[j*16 + q] = combp[j];
            #pragma unroll 4
            for (int c = 0; c < 8; c++)
                xw[(49 + c)*16 + q] = semb[(size_t)c*HWP];
        } else {
            #pragma unroll 4
            for (int c = 8; c < 64; c++)
                xw[(49 + c)*16 + q] = semb[(size_t)c*HWP];
        }
    }
    __syncwarp();

    float y0[16], y1[16];
    #pragma unroll
    for (int q = 0; q < 16; q++) { y0[q] = b1_0; y1[q] = b1_1; }

    #pragma unroll 2
    for (int j = 0; j < 113; j++) {
        float2 a = __ldg(&g_w1f[j*32 + lane]);
        float4 xA = *(const float4*)(xw + j*16);
        float4 xB = *(const float4*)(xw + j*16 + 4);
        float4 xC = *(const float4*)(xw + j*16 + 8);
        float4 xD = *(const float4*)(xw + j*16 + 12);
        ACC32(a, xA, xB, xC, xD)
    }

    {
        float h0[16], h1[16];
        #pragma unroll
        for (int q = 0; q < 16; q++) {
            float s = y0[q] + (has2 ? y1[q] : 0.f);
            float t = y0[q]*y0[q] + (has2 ? y1[q]*y1[q] : 0.f);
            #pragma unroll
            for (int o = 16; o; o >>= 1) {
                s += __shfl_xor_sync(0xffffffffu, s, o);
                t += __shfl_xor_sync(0xffffffffu, t, o);
            }
            float mean = s * (1.f/49.f);
            float rstd = rsqrtf(t * (1.f/49.f) - mean*mean + 1e-6f);
            float a0 = g_0 * (y0[q]-mean) * rstd + be_0;
            float a1 = g_1 * (y1[q]-mean) * rstd + be_1;
            h0[q] = a0 / (1.f + __expf(-a0));
            h1[q] = a1 / (1.f + __expf(-a1));
        }
        __syncwarp();
        *(float4*)&xw[lane*16]      = make_float4(h0[0],h0[1],h0[2],h0[3]);
        *(float4*)&xw[lane*16 + 4]  = make_float4(h0[4],h0[5],h0[6],h0[7]);
        *(float4*)&xw[lane*16 + 8]  = make_float4(h0[8],h0[9],h0[10],h0[11]);
        *(float4*)&xw[lane*16 + 12] = make_float4(h0[12],h0[13],h0[14],h0[15]);
        if (has2) {
            *(float4*)&xw[(lane+32)*16]      = make_float4(h1[0],h1[1],h1[2],h1[3]);
            *(float4*)&xw[(lane+32)*16 + 4]  = make_float4(h1[4],h1[5],h1[6],h1[7]);
            *(float4*)&xw[(lane+32)*16 + 8]  = make_float4(h1[8],h1[9],h1[10],h1[11]);
            *(float4*)&xw[(lane+32)*16 +12]  = make_float4(h1[12],h1[13],h1[14],h1[15]);
        }
        __syncwarp();
    }

    #pragma unroll
    for (int q = 0; q < 16; q++) { y0[q] = b2_0; y1[q] = b2_1; }
    #pragma unroll 2
    for (int j = 0; j < 49; j++) {
        float2 a = __ldg(&g_w2f[j*32 + lane]);
        float4 xA = *(const float4*)(xw + j*16);
        float4 xB = *(const float4*)(xw + j*16 + 4);
        float4 xC = *(const float4*)(xw + j*16 + 8);
        float4 xD = *(const float4*)(xw + j*16 + 12);
        ACC32(a, xA, xB, xC, xD)
    }

    #pragma unroll
    for (int q = 0; q < 16; q++) {
        int p = pbase + q;
        float cb0 = g_comb[(size_t)p*N2 + lane];
        float cb1 = has2 ? g_comb[(size_t)p*N2 + lane + 32] : 0.f;
        float wv0 = cb0 * (1.f + 1.f/(1.f + __expf(-y0[q])));
        float wv1 = has2 ? cb1 * (1.f + 1.f/(1.f + __expf(-y1[q]))) : 0.f;
        float ss = wv0 + wv1;
        #pragma unroll
        for (int o = 16; o; o >>= 1) ss += __shfl_xor_sync(0xffffffffu, ss, o);
        float inv = 1.f / (ss + 1e-7f);
        g_comb[(size_t)p*N2 + lane] = wv0 * inv;
        if (has2) g_comb[(size_t)p*N2 + lane + 32] = wv1 * inv;
    }
}

// ---------------------------------------------------------------------------
// K3b: weighted neighborhood reduction + output_proj, weights via LDG.
// 8 px/warp; gather clamped predicate-free.
// ---------------------------------------------------------------------------
__global__ __launch_bounds__(256, 4) void k_output(
    const float* __restrict__ b1, const float* __restrict__ g,
    const float* __restrict__ be, const float* __restrict__ b2,
    float* __restrict__ out)
{
    extern __shared__ float sm[];
    float* wsb = sm;                        // [8][52]
    float* os  = sm + 416;                  // [8][64][8]
    int tid = threadIdx.x, lane = tid & 31, w = tid >> 5;

    float b1_0 = b1[lane], b1_1 = b1[lane+32];
    float g_0  = g[lane],  g_1  = g[lane+32];
    float be_0 = be[lane], be_1 = be[lane+32];
    float b2_0 = b2[lane], b2_1 = b2[lane+32];

    int pbase = blockIdx.x * 64 + w * 8;
    float* ow   = os  + w * 512;
    float* wrow = wsb + w * 52;

    {
        float a0[8], a1[8];
        for (int q = 0; q < 8; q++) {
            int p = pbase + q;
            int b = p / HWP, pp = p % HWP, yy = pp / WW, xx = pp % WW;

            for (int n = lane; n < N2; n += 32) wrow[n] = g_comb[(size_t)p*N2 + n];
            __syncwarp();

            float s0 = 0.f, s1 = 0.f;
            int n = 0;
            #pragma unroll
            for (int dy = -3; dy <= 3; dy++) {
                int ny = min(max(yy + dy, 0), HH-1);
                const float* rbase = &g_spa_t[(b*HWP + ny*WW)*CC + lane*2];
                #pragma unroll
                for (int dx = -3; dx <= 3; dx++, n++) {
                    int nx = min(max(xx + dx, 0), WW-1);
                    float wv = wrow[n];
                    float2 sv = *(const float2*)(rbase + nx*CC);
                    s0 += sv.x * wv;
                    s1 += sv.y * wv;
                }
            }
            a0[q] = s0; a1[q] = s1;
            __syncwarp();
        }
        *(float4*)&ow[(lane*2)*8]       = make_float4(a0[0],a0[1],a0[2],a0[3]);
        *(float4*)&ow[(lane*2)*8 + 4]   = make_float4(a0[4],a0[5],a0[6],a0[7]);
        *(float4*)&ow[(lane*2+1)*8]     = make_float4(a1[0],a1[1],a1[2],a1[3]);
        *(float4*)&ow[(lane*2+1)*8 + 4] = make_float4(a1[4],a1[5],a1[6],a1[7]);
        __syncwarp();
    }

    float y0[8], y1[8];
    #pragma unroll
    for (int q = 0; q < 8; q++) { y0[q] = b1_0; y1[q] = b1_1; }
    #pragma unroll 4
    for (int c = 0; c < 64; c++) {
        float2 a = __ldg(&g_w1o[c*32 + lane]);
        float4 xa = *(const float4*)(ow + c*8);
        float4 xb = *(const float4*)(ow + c*8 + 4);
        y0[0]+=a.x*xa.x; y1[0]+=a.y*xa.x;
        y0[1]+=a.x*xa.y; y1[1]+=a.y*xa.y;
        y0[2]+=a.x*xa.z; y1[2]+=a.y*xa.z;
        y0[3]+=a.x*xa.w; y1[3]+=a.y*xa.w;
        y0[4]+=a.x*xb.x; y1[4]+=a.y*xb.x;
        y0[5]+=a.x*xb.y; y1[5]+=a.y*xb.y;
        y0[6]+=a.x*xb.z; y1[6]+=a.y*xb.z;
        y0[7]+=a.x*xb.w; y1[7]+=a.y*xb.w;
    }

    {
        float h0[8], h1[8];
        #pragma unroll
        for (int q = 0; q < 8; q++) {
            float s = y0[q] + y1[q];
            float t = y0[q]*y0[q] + y1[q]*y1[q];
            #pragma unroll
            for (int o = 16; o; o >>= 1) {
                s += __shfl_xor_sync(0xffffffffu, s, o);
                t += __shfl_xor_sync(0xffffffffu, t, o);
            }
            float mean = s * (1.f/64.f);
            float rstd = rsqrtf(t * (1.f/64.f) - mean*mean + 1e-6f);
            h0[q] = g_0 * (y0[q]-mean) * rstd + be_0;
            h1[q] = g_1 * (y1[q]-mean) * rstd + be_1;
        }
        __syncwarp();
        *(float4*)&ow[lane*8]          = make_float4(h0[0],h0[1],h0[2],h0[3]);
        *(float4*)&ow[lane*8 + 4]      = make_float4(h0[4],h0[5],h0[6],h0[7]);
        *(float4*)&ow[(lane+32)*8]     = make_float4(h1[0],h1[1],h1[2],h1[3]);
        *(float4*)&ow[(lane+32)*8 + 4] = make_float4(h1[4],h1[5],h1[6],h1[7]);
        __syncwarp();
    }

    #pragma unroll
    for (int q = 0; q < 8; q++) { y0[q] = b2_0; y1[q] = b2_1; }
    #pragma unroll 4
    for (int c = 0; c < 64; c++) {
        float2 a = __ldg(&g_w2o[c*32 + lane]);
        float4 xa = *(const float4*)(ow + c*8);
        float4 xb = *(const float4*)(ow + c*8 + 4);
        y0[0]+=a.x*xa.x; y1[0]+=a.y*xa.x;
        y0[1]+=a.x*xa.y; y1[1]+=a.y*xa.y;
        y0[2]+=a.x*xa.z; y1[2]+=a.y*xa.z;
        y0[3]+=a.x*xa.w; y1[3]+=a.y*xa.w;
        y0[4]+=a.x*xb.x; y1[4]+=a.y*xb.x;
        y0[5]+=a.x*xb.y; y1[5]+=a.y*xb.y;
        y0[6]+=a.x*xb.z; y1[6]+=a.y*xb.z;
        y0[7]+=a.x*xb.w; y1[7]+=a.y*xb.w;
    }

    #pragma unroll
    for (int q = 0; q < 8; q++) {
        int p = pbase + q;
        int b = p / HWP, pp = p % HWP;
        out[(b*CC + lane)*HWP + pp]      = y0[q];
        out[(b*CC + lane + 32)*HWP + pp] = y1[q];
    }
}

// ---------------------------------------------------------------------------
extern "C" void kernel_launch(void* const* d_in, const int* in_sizes, int n_in,
                              void* d_out, int out_size)
{
    const float* spa = (const float*)d_in[0];
    const float* sem = (const float*)d_in[1];

    static bool attr_set = false;
    if (!attr_set) {
        cudaFuncSetAttribute(k_range,  cudaFuncAttributeMaxDynamicSharedMemorySize, 16384);
        cudaFuncSetAttribute(k_fixup,  cudaFuncAttributeMaxDynamicSharedMemorySize, 28928);
        cudaFuncSetAttribute(k_output, cudaFuncAttributeMaxDynamicSharedMemorySize, 18048);
        attr_set = true;
    }

    k_prep<<<15, 256>>>((const float*)d_in[2], (const float*)d_in[6],
                        (const float*)d_in[8], (const float*)d_in[12],
                        (const float*)d_in[14], (const float*)d_in[18]);

    dim3 tg(HWP/32, CC/32, BB), tb(32, 8);
    k_transpose<<<tg, tb>>>(spa);

    k_range<<<NPIX/64, 128, 16384>>>(sem,
                                     (const float*)d_in[3],
                                     (const float*)d_in[4], (const float*)d_in[5],
                                     (const float*)d_in[7]);

    // warps = (NPIX/32) * 7 = 5488 ; 8 warps/block -> 686 blocks
    k_bilateral<<<686, 256>>>((const float*)d_in[20]);

    k_fixup<<<NPIX/64, 128, 28928>>>(sem,
                                     (const float*)d_in[9],
                                     (const float*)d_in[10], (const float*)d_in[11],
                                     (const float*)d_in[13]);

    k_output<<<NPIX/64, 256, 18048>>>((const float*)d_in[15],
                                      (const float*)d_in[16], (const float*)d_in[17],
                                      (const float*)d_in[19],
                                      (float*)d_out);
}

// round 15
// speedup vs baseline: 1.4933x; 1.2020x over previous
#include <cuda_runtime.h>

// ---------------------------------------------------------------------------
// SpatialRangeAttention — GB300 sm_103a
// ---------------------------------------------------------------------------

#define BB   2
#define CC   64
#define HH   112
#define WW   112
#define HWP  (HH*WW)      // 12544
#define NPIX (BB*HWP)     // 25088
#define N2   49

// Scratch
__device__ float g_spa_t[NPIX*CC];   // spatial transposed [pix][c]
__device__ float g_px_cm[NPIX*CC];   // range-projected, CHANNEL-major [b][c][hw]
__device__ float g_nrm[NPIX];        // per-pixel ||px||^2
__device__ float g_comb[NPIX*N2];    // bilateral / final weights [pix][n]

// Interleaved weight buffers (shared by all blocks; L1/L2-resident)
__device__ float2 g_w1r[64*32], g_w2r[64*32];   // range
__device__ float2 g_w1f[113*32], g_w2f[49*32];  // fixup (zero-padded o>=49)
__device__ float2 g_w1o[64*32], g_w2o[64*32];   // output

// 16-FMA block: weight pair a=(w[o],w[o+32]) times 8 pixel x-values
#define ACC16(a, xa, xb)                              \
    y0[0]+=a.x*xa.x; y1[0]+=a.y*xa.x;                 \
    y0[1]+=a.x*xa.y; y1[1]+=a.y*xa.y;                 \
    y0[2]+=a.x*xa.z; y1[2]+=a.y*xa.z;                 \
    y0[3]+=a.x*xa.w; y1[3]+=a.y*xa.w;                 \
    y0[4]+=a.x*xb.x; y1[4]+=a.y*xb.x;                 \
    y0[5]+=a.x*xb.y; y1[5]+=a.y*xb.y;                 \
    y0[6]+=a.x*xb.z; y1[6]+=a.y*xb.z;                 \
    y0[7]+=a.x*xb.w; y1[7]+=a.y*xb.w;

// 8-FMA block: weight pair times 4 pixel x-values
#define ACC8(a, xa)                                   \
    y0[0]+=a.x*xa.x; y1[0]+=a.y*xa.x;                 \
    y0[1]+=a.x*xa.y; y1[1]+=a.y*xa.y;                 \
    y0[2]+=a.x*xa.z; y1[2]+=a.y*xa.z;                 \
    y0[3]+=a.x*xa.w; y1[3]+=a.y*xa.w;

// ---------------------------------------------------------------------------
// K-1: prep — interleave all conv weights into global float2 buffers
// ---------------------------------------------------------------------------
__global__ __launch_bounds__(256) void k_prep(
    const float* __restrict__ rw1, const float* __restrict__ rw2,
    const float* __restrict__ fw1, const float* __restrict__ fw2,
    const float* __restrict__ ow1, const float* __restrict__ ow2)
{
    int i = blockIdx.x * 256 + threadIdx.x;
    if (i < 2048) {
        int c = i >> 5, l = i & 31;
        g_w1r[i] = make_float2(rw1[l*64 + c], rw1[(l+32)*64 + c]);
        g_w2r[i] = make_float2(rw2[l*64 + c], rw2[(l+32)*64 + c]);
        g_w1o[i] = make_float2(ow1[l*64 + c], ow1[(l+32)*64 + c]);
        g_w2o[i] = make_float2(ow2[l*64 + c], ow2[(l+32)*64 + c]);
    }
    if (i < 113*32) {
        int j = i >> 5, l = i & 31;
        g_w1f[i] = make_float2((l    < N2) ? fw1[l*113 + j]      : 0.f,
                               (l+32 < N2) ? fw1[(l+32)*113 + j] : 0.f);
    }
    if (i < 49*32) {
        int j = i >> 5, l = i & 31;
        g_w2f[i] = make_float2((l    < N2) ? fw2[l*49 + j]      : 0.f,
                               (l+32 < N2) ? fw2[(l+32)*49 + j] : 0.f);
    }
}

// ---------------------------------------------------------------------------
// K0: transpose spatial input [B,C,HW] -> [B*HW, C]
// ---------------------------------------------------------------------------
__global__ __launch_bounds__(256) void k_transpose(const float* __restrict__ spa)
{
    __shared__ float t1[32][33];
    int b  = blockIdx.z;
    int c0 = blockIdx.y * 32;
    int p0 = blockIdx.x * 32;
    int tx = threadIdx.x, ty = threadIdx.y;
    #pragma unroll
    for (int i = ty; i < 32; i += 8)
        t1[i][tx] = spa[(b*CC + c0 + i)*HWP + p0 + tx];
    __syncthreads();
    #pragma unroll
    for (int i = ty; i < 32; i += 8)
        g_spa_t[(b*HWP + p0 + i)*CC + c0 + tx] = t1[tx][i];
}

// ---------------------------------------------------------------------------
// K1: range_proj. 8 px/warp, 16 accumulators, weights via LDG.
// 128 threads, grid NPIX/32 = 784 -> 21 warps/SM.
// ---------------------------------------------------------------------------
__global__ __launch_bounds__(128, 8) void k_range(
    const float* __restrict__ sem,
    const float* __restrict__ b1, const float* __restrict__ g,
    const float* __restrict__ be, const float* __restrict__ b2)
{
    extern __shared__ float sm[];
    float* xs = sm;                          // [4 warps][64 rows][8 px]
    int tid = threadIdx.x, lane = tid & 31, w = tid >> 5;

    float b1_0 = b1[lane], b1_1 = b1[lane+32];
    float g_0  = g[lane],  g_1  = g[lane+32];
    float be_0 = be[lane], be_1 = be[lane+32];
    float b2_0 = b2[lane], b2_1 = b2[lane+32];

    int pbase = blockIdx.x * 32 + w * 8;
    int bI = pbase / HWP, ppb = pbase % HWP;
    float* xw = xs + w * 512;

    // stage 8 pixels from channel-major sem: lane = (q = lane&7, grp = lane>>3)
    {
        int q = lane & 7, grp = lane >> 3;
        const float* semb = sem + (size_t)bI*CC*HWP + ppb + q;
        #pragma unroll 4
        for (int i = 0; i < 16; i++) {
            int c = grp*16 + i;
            xw[c*8 + q] = semb[(size_t)c*HWP];
        }
    }
    __syncwarp();

    float y0[8], y1[8];
    #pragma unroll
    for (int q = 0; q < 8; q++) { y0[q] = b1_0; y1[q] = b1_1; }

    #pragma unroll 4
    for (int c = 0; c < 64; c++) {
        float2 a = __ldg(&g_w1r[c*32 + lane]);
        float4 xa = *(const float4*)(xw + c*8);
        float4 xb = *(const float4*)(xw + c*8 + 4);
        ACC16(a, xa, xb)
    }

    {
        float h0[8], h1[8];
        #pragma unroll
        for (int q = 0; q < 8; q++) {
            float s = y0[q] + y1[q];
            float t = y0[q]*y0[q] + y1[q]*y1[q];
            #pragma unroll
            for (int o = 16; o; o >>= 1) {
                s += __shfl_xor_sync(0xffffffffu, s, o);
                t += __shfl_xor_sync(0xffffffffu, t, o);
            }
            float mean = s * (1.f/64.f);
            float rstd = rsqrtf(t * (1.f/64.f) - mean*mean + 1e-6f);
            float a0 = g_0 * (y0[q]-mean) * rstd + be_0;
            float a1 = g_1 * (y1[q]-mean) * rstd + be_1;
            h0[q] = a0 / (1.f + __expf(-a0));
            h1[q] = a1 / (1.f + __expf(-a1));
        }
        __syncwarp();
        *(float4*)&xw[lane*8]          = make_float4(h0[0],h0[1],h0[2],h0[3]);
        *(float4*)&xw[lane*8 + 4]      = make_float4(h0[4],h0[5],h0[6],h0[7]);
        *(float4*)&xw[(lane+32)*8]     = make_float4(h1[0],h1[1],h1[2],h1[3]);
        *(float4*)&xw[(lane+32)*8 + 4] = make_float4(h1[4],h1[5],h1[6],h1[7]);
        __syncwarp();
    }

    #pragma unroll
    for (int q = 0; q < 8; q++) { y0[q] = b2_0; y1[q] = b2_1; }
    #pragma unroll 4
    for (int c = 0; c < 64; c++) {
        float2 a = __ldg(&g_w2r[c*32 + lane]);
        float4 xa = *(const float4*)(xw + c*8);
        float4 xb = *(const float4*)(xw + c*8 + 4);
        ACC16(a, xa, xb)
    }

    #pragma unroll
    for (int q = 0; q < 8; q++) {
        float t = y0[q]*y0[q] + y1[q]*y1[q];
        #pragma unroll
        for (int o = 16; o; o >>= 1) t += __shfl_xor_sync(0xffffffffu, t, o);
        if (lane == 0) g_nrm[pbase + q] = t;
    }
    {
        float* d0 = &g_px_cm[(size_t)(bI*CC + lane)*HWP + ppb];
        *(float4*)d0       = make_float4(y0[0],y0[1],y0[2],y0[3]);
        *(float4*)(d0 + 4) = make_float4(y0[4],y0[5],y0[6],y0[7]);
        float* d1 = &g_px_cm[(size_t)(bI*CC + lane + 32)*HWP + ppb];
        *(float4*)d1       = make_float4(y1[0],y1[1],y1[2],y1[3]);
        *(float4*)(d1 + 4) = make_float4(y1[4],y1[5],y1[6],y1[7]);
    }
}

// ---------------------------------------------------------------------------
// K2: bilateral (R9-exact): dist2 = |n|^2+|c|^2-2dot. Warp = (32 pixels, dy).
// ---------------------------------------------------------------------------
__global__ __launch_bounds__(256) void k_bilateral(const float* __restrict__ sigma)
{
    int wid  = (blockIdx.x << 3) + (threadIdx.x >> 5);
    int lane = threadIdx.x & 31;
    int gpix = wid / 7;
    int dyi  = wid - gpix*7;
    int dy   = dyi - 3;

    int p  = (gpix << 5) + lane;
    int b  = p / HWP, pp = p % HWP, yy = pp / WW, xx = pp % WW;
    int ny = yy + dy;
    bool rowok = ((unsigned)ny < HH);
    int nrow = (rowok ? ny : yy) * WW;

    const float* base = g_px_cm + (size_t)b * (CC*HWP);

    int off[7]; unsigned okm = 0;
    #pragma unroll
    for (int i = 0; i < 7; i++) {
        int nx = xx + i - 3;
        bool o = rowok & ((unsigned)nx < WW);
        okm |= (o ? 1u : 0u) << i;
        off[i] = nrow + (o ? nx : xx);
    }

    float acc[7] = {0.f,0.f,0.f,0.f,0.f,0.f,0.f};
    #pragma unroll 4
    for (int c = 0; c < CC; c++) {
        const float* rc = base + c*HWP;
        float cv = rc[pp];
        #pragma unroll
        for (int i = 0; i < 7; i++) acc[i] += cv * rc[off[i]];
    }

    float nc = g_nrm[p];
    float sg = *sigma;
    float is2 = 0.5f / (sg*sg);
    float* outp = &g_comb[(size_t)p*N2 + dyi*7];
    const float* nrmb = &g_nrm[b*HWP];
    #pragma unroll
    for (int i = 0; i < 7; i++) {
        float res = 0.f;
        if ((okm >> i) & 1u) {
            float d2 = fmaxf(nrmb[off[i]] + nc - 2.f*acc[i], 0.f);
            float fdx = (float)(i - 3);
            res = __expf(-d2*(1.f/128.f) - ((float)(dy*dy) + fdx*fdx)*is2);
        }
        outp[i] = res;
    }
}

// ---------------------------------------------------------------------------
// K3a: fixup. 8 px/warp, 16 accumulators, weights via LDG.
// 128 threads, grid NPIX/32 = 784 -> 21 warps/SM. smem 14464B/block.
// ---------------------------------------------------------------------------
__global__ __launch_bounds__(128, 8) void k_fixup(
    const float* __restrict__ sem,
    const float* __restrict__ b1, const float* __restrict__ g,
    const float* __restrict__ be, const float* __restrict__ b2)
{
    extern __shared__ float sm[];
    float* xs = sm;                          // [4 warps][113][8]
    int tid = threadIdx.x, lane = tid & 31, w = tid >> 5;

    const bool has2 = (lane + 32) < N2;
    float b1_0 = (lane < N2) ? b1[lane] : 0.f;
    float b1_1 = has2 ? b1[lane+32] : 0.f;
    float g_0  = (lane < N2) ? g[lane]  : 0.f;
    float g_1  = has2 ? g[lane+32]  : 0.f;
    float be_0 = (lane < N2) ? be[lane] : 0.f;
    float be_1 = has2 ? be[lane+32] : 0.f;
    float b2_0 = (lane < N2) ? b2[lane] : 0.f;
    float b2_1 = has2 ? b2[lane+32] : 0.f;

    int pbase = blockIdx.x * 32 + w * 8;
    int bI = pbase / HWP, ppb = pbase % HWP;
    float* xw = xs + w * 904;

    // stage: lane = (q = lane&7, grp = lane>>3); grp g covers j-range of ~29
    {
        int q = lane & 7, grp = lane >> 3;
        const float* combp = g_comb + (size_t)(pbase + q)*N2;
        const float* semb  = sem + (size_t)bI*CC*HWP + ppb + q;
        int j0 = grp * 29;
        int j1 = (grp == 3) ? 113 : j0 + 29;
        for (int j = j0; j < j1; j++) {
            float v = (j < N2) ? combp[j] : semb[(size_t)(j - N2)*HWP];
            xw[j*8 + q] = v;
        }
    }
    __syncwarp();

    float y0[8], y1[8];
    #pragma unroll
    for (int q = 0; q < 8; q++) { y0[q] = b1_0; y1[q] = b1_1; }

    #pragma unroll 4
    for (int j = 0; j < 113; j++) {
        float2 a = __ldg(&g_w1f[j*32 + lane]);
        float4 xa = *(const float4*)(xw + j*8);
        float4 xb = *(const float4*)(xw + j*8 + 4);
        ACC16(a, xa, xb)
    }

    {
        float h0[8], h1[8];
        #pragma unroll
        for (int q = 0; q < 8; q++) {
            float s = y0[q] + (has2 ? y1[q] : 0.f);
            float t = y0[q]*y0[q] + (has2 ? y1[q]*y1[q] : 0.f);
            #pragma unroll
            for (int o = 16; o; o >>= 1) {
                s += __shfl_xor_sync(0xffffffffu, s, o);
                t += __shfl_xor_sync(0xffffffffu, t, o);
            }
            float mean = s * (1.f/49.f);
            float rstd = rsqrtf(t * (1.f/49.f) - mean*mean + 1e-6f);
            float a0 = g_0 * (y0[q]-mean) * rstd + be_0;
            float a1 = g_1 * (y1[q]-mean) * rstd + be_1;
            h0[q] = a0 / (1.f + __expf(-a0));
            h1[q] = a1 / (1.f + __expf(-a1));
        }
        __syncwarp();
        *(float4*)&xw[lane*8]     = make_float4(h0[0],h0[1],h0[2],h0[3]);
        *(float4*)&xw[lane*8 + 4] = make_float4(h0[4],h0[5],h0[6],h0[7]);
        if (has2) {
            *(float4*)&xw[(lane+32)*8]     = make_float4(h1[0],h1[1],h1[2],h1[3]);
            *(float4*)&xw[(lane+32)*8 + 4] = make_float4(h1[4],h1[5],h1[6],h1[7]);
        }
        __syncwarp();
    }

    #pragma unroll
    for (int q = 0; q < 8; q++) { y0[q] = b2_0; y1[q] = b2_1; }
    #pragma unroll 4
    for (int j = 0; j < 49; j++) {
        float2 a = __ldg(&g_w2f[j*32 + lane]);
        float4 xa = *(const float4*)(xw + j*8);
        float4 xb = *(const float4*)(xw + j*8 + 4);
        ACC16(a, xa, xb)
    }

    #pragma unroll
    for (int q = 0; q < 8; q++) {
        int p = pbase + q;
        float cb0 = g_comb[(size_t)p*N2 + lane];
        float cb1 = has2 ? g_comb[(size_t)p*N2 + lane + 32] : 0.f;
        float wv0 = cb0 * (1.f + 1.f/(1.f + __expf(-y0[q])));
        float wv1 = has2 ? cb1 * (1.f + 1.f/(1.f + __expf(-y1[q]))) : 0.f;
        float ss = wv0 + wv1;
        #pragma unroll
        for (int o = 16; o; o >>= 1) ss += __shfl_xor_sync(0xffffffffu, ss, o);
        float inv = 1.f / (ss + 1e-7f);
        g_comb[(size_t)p*N2 + lane] = wv0 * inv;
        if (has2) g_comb[(size_t)p*N2 + lane + 32] = wv1 * inv;
    }
}

// ---------------------------------------------------------------------------
// K3b: weighted neighborhood reduction + output_proj, weights via LDG.
// 4 px/warp, 128 threads, grid NPIX/16 = 1568 -> ~32-40 warps/SM.
// ---------------------------------------------------------------------------
__global__ __launch_bounds__(128, 10) void k_output(
    const float* __restrict__ b1, const float* __restrict__ g,
    const float* __restrict__ be, const float* __restrict__ b2,
    float* __restrict__ out)
{
    extern __shared__ float sm[];
    float* wsb = sm;                        // [4][52]
    float* os  = sm + 208;                  // [4 warps][64][4]
    int tid = threadIdx.x, lane = tid & 31, w = tid >> 5;

    float b1_0 = b1[lane], b1_1 = b1[lane+32];
    float g_0  = g[lane],  g_1  = g[lane+32];
    float be_0 = be[lane], be_1 = be[lane+32];
    float b2_0 = b2[lane], b2_1 = b2[lane+32];

    int pbase = blockIdx.x * 16 + w * 4;
    int bI = pbase / HWP, ppb = pbase % HWP;
    float* ow   = os  + w * 256;
    float* wrow = wsb + w * 52;

    // Gather: lane owns channels (2*lane, 2*lane+1); clamped, predicate-free
    {
        float a0[4], a1[4];
        #pragma unroll
        for (int q = 0; q < 4; q++) {
            int pp = ppb + q;
            int yy = pp / WW, xx = pp % WW;

            for (int n = lane; n < N2; n += 32) wrow[n] = g_comb[(size_t)(pbase+q)*N2 + n];
            __syncwarp();

            float s0 = 0.f, s1 = 0.f;
            int n = 0;
            #pragma unroll
            for (int dy = -3; dy <= 3; dy++) {
                int ny = min(max(yy + dy, 0), HH-1);
                const float* rbase = &g_spa_t[(size_t)(bI*HWP + ny*WW)*CC + lane*2];
                #pragma unroll
                for (int dx = -3; dx <= 3; dx++, n++) {
                    int nx = min(max(xx + dx, 0), WW-1);
                    float wv = wrow[n];                  // 0 for OOB neighbors
                    float2 sv = *(const float2*)(rbase + nx*CC);
                    s0 += sv.x * wv;
                    s1 += sv.y * wv;
                }
            }
            a0[q] = s0; a1[q] = s1;
            __syncwarp();
        }
        *(float4*)&ow[(lane*2)*4]   = make_float4(a0[0],a0[1],a0[2],a0[3]);
        *(float4*)&ow[(lane*2+1)*4] = make_float4(a1[0],a1[1],a1[2],a1[3]);
        __syncwarp();
    }

    float y0[4], y1[4];
    #pragma unroll
    for (int q = 0; q < 4; q++) { y0[q] = b1_0; y1[q] = b1_1; }
    #pragma unroll 4
    for (int c = 0; c < 64; c++) {
        float2 a = __ldg(&g_w1o[c*32 + lane]);
        float4 xa = *(const float4*)(ow + c*4);
        ACC8(a, xa)
    }

    {
        float h0[4], h1[4];
        #pragma unroll
        for (int q = 0; q < 4; q++) {
            float s = y0[q] + y1[q];
            float t = y0[q]*y0[q] + y1[q]*y1[q];
            #pragma unroll
            for (int o = 16; o; o >>= 1) {
                s += __shfl_xor_sync(0xffffffffu, s, o);
                t += __shfl_xor_sync(0xffffffffu, t, o);
            }
            float mean = s * (1.f/64.f);
            float rstd = rsqrtf(t * (1.f/64.f) - mean*mean + 1e-6f);
            h0[q] = g_0 * (y0[q]-mean) * rstd + be_0;
            h1[q] = g_1 * (y1[q]-mean) * rstd + be_1;
        }
        __syncwarp();
        *(float4*)&ow[lane*4]      = make_float4(h0[0],h0[1],h0[2],h0[3]);
        *(float4*)&ow[(lane+32)*4] = make_float4(h1[0],h1[1],h1[2],h1[3]);
        __syncwarp();
    }

    #pragma unroll
    for (int q = 0; q < 4; q++) { y0[q] = b2_0; y1[q] = b2_1; }
    #pragma unroll 4
    for (int c = 0; c < 64; c++) {
        float2 a = __ldg(&g_w2o[c*32 + lane]);
        float4 xa = *(const float4*)(ow + c*4);
        ACC8(a, xa)
    }

    {
        float* d0 = &out[(size_t)(bI*CC + lane)*HWP + ppb];
        *(float4*)d0 = make_float4(y0[0],y0[1],y0[2],y0[3]);
        float* d1 = &out[(size_t)(bI*CC + lane + 32)*HWP + ppb];
        *(float4*)d1 = make_float4(y1[0],y1[1],y1[2],y1[3]);
    }
}

// ---------------------------------------------------------------------------
extern "C" void kernel_launch(void* const* d_in, const int* in_sizes, int n_in,
                              void* d_out, int out_size)
{
    const float* spa = (const float*)d_in[0];
    const float* sem = (const float*)d_in[1];

    static bool attr_set = false;
    if (!attr_set) {
        cudaFuncSetAttribute(k_range,  cudaFuncAttributeMaxDynamicSharedMemorySize, 8192);
        cudaFuncSetAttribute(k_fixup,  cudaFuncAttributeMaxDynamicSharedMemorySize, 14464);
        cudaFuncSetAttribute(k_output, cudaFuncAttributeMaxDynamicSharedMemorySize, 4928);
        attr_set = true;
    }

    k_prep<<<15, 256>>>((const float*)d_in[2], (const float*)d_in[6],
                        (const float*)d_in[8], (const float*)d_in[12],
                        (const float*)d_in[14], (const float*)d_in[18]);

    dim3 tg(HWP/32, CC/32, BB), tb(32, 8);
    k_transpose<<<tg, tb>>>(spa);

    k_range<<<NPIX/32, 128, 8192>>>(sem,
                                    (const float*)d_in[3],
                                    (const float*)d_in[4], (const float*)d_in[5],
                                    (const float*)d_in[7]);

    // warps = (NPIX/32) * 7 = 5488 ; 8 warps/block -> 686 blocks
    k_bilateral<<<686, 256>>>((const float*)d_in[20]);

    k_fixup<<<NPIX/32, 128, 14464>>>(sem,
                                     (const float*)d_in[9],
                                     (const float*)d_in[10], (const float*)d_in[11],
                                     (const float*)d_in[13]);

    k_output<<<NPIX/16, 128, 4928>>>((const float*)d_in[15],
                                     (const float*)d_in[16], (const float*)d_in[17],
                                     (const float*)d_in[19],
                                     (float*)d_out);
}